// round 1
// baseline (speedup 1.0000x reference)
#include <cuda_runtime.h>
#include <math.h>

// Problem dims (fixed)
#define BATCH 4
#define SEQ   2048
#define DMOD  1024      // = H*DK = H*DV
#define NHEAD 16
#define HDIM  64

#define MROWS (BATCH*SEQ)   // 8192

// Scratch (device globals; no allocation allowed)
__device__ float g_Q[BATCH*SEQ*DMOD];
__device__ float g_K[BATCH*SEQ*DMOD];
__device__ float g_V[BATCH*SEQ*DMOD];
__device__ float g_A[BATCH*SEQ*DMOD];

// ---------------------------------------------------------------------------
// SGEMM: C[M,N] = A[M,K] @ B[K,N], fp32, 128x128x16 tiles, 8x8 micro-tiles
// M,N,K all multiples of tile dims here (8192/1024/1024).
// ---------------------------------------------------------------------------
__global__ __launch_bounds__(256) void sgemm128(
    const float* __restrict__ A, const float* __restrict__ B,
    float* __restrict__ C, int M, int N, int K)
{
    __shared__ float As[16 * 128];   // As[k][m]
    __shared__ float Bs[16 * 128];   // Bs[k][n]

    const int tid = threadIdx.x;
    const int bm = blockIdx.y * 128;
    const int bn = blockIdx.x * 128;

    const int tx = tid & 15;   // n-dir, 16
    const int ty = tid >> 4;   // m-dir, 16

    // A-tile load mapping: 128 rows x 16 k; each thread 2x float4
    const int ar = tid >> 2;          // 0..63
    const int ak = (tid & 3) * 4;     // 0,4,8,12
    // B-tile load mapping: 16 k x 128 n; each thread 2x float4
    const int br = tid >> 5;          // 0..7
    const int bc = (tid & 31) * 4;    // 0..124

    float acc[8][8];
    #pragma unroll
    for (int i = 0; i < 8; i++)
        #pragma unroll
        for (int j = 0; j < 8; j++) acc[i][j] = 0.f;

    for (int k0 = 0; k0 < K; k0 += 16) {
        float4 a0 = *(const float4*)&A[(long)(bm + ar) * K + k0 + ak];
        float4 a1 = *(const float4*)&A[(long)(bm + ar + 64) * K + k0 + ak];
        float4 b0 = *(const float4*)&B[(long)(k0 + br) * N + bn + bc];
        float4 b1 = *(const float4*)&B[(long)(k0 + br + 8) * N + bn + bc];

        // store A transposed: As[k][m]
        As[(ak + 0) * 128 + ar] = a0.x;
        As[(ak + 1) * 128 + ar] = a0.y;
        As[(ak + 2) * 128 + ar] = a0.z;
        As[(ak + 3) * 128 + ar] = a0.w;
        As[(ak + 0) * 128 + ar + 64] = a1.x;
        As[(ak + 1) * 128 + ar + 64] = a1.y;
        As[(ak + 2) * 128 + ar + 64] = a1.z;
        As[(ak + 3) * 128 + ar + 64] = a1.w;
        *(float4*)&Bs[br * 128 + bc] = b0;
        *(float4*)&Bs[(br + 8) * 128 + bc] = b1;
        __syncthreads();

        #pragma unroll
        for (int kk = 0; kk < 16; kk++) {
            float ra[8], rb[8];
            *(float4*)&ra[0] = *(const float4*)&As[kk * 128 + ty * 8];
            *(float4*)&ra[4] = *(const float4*)&As[kk * 128 + ty * 8 + 4];
            *(float4*)&rb[0] = *(const float4*)&Bs[kk * 128 + tx * 8];
            *(float4*)&rb[4] = *(const float4*)&Bs[kk * 128 + tx * 8 + 4];
            #pragma unroll
            for (int i = 0; i < 8; i++)
                #pragma unroll
                for (int j = 0; j < 8; j++)
                    acc[i][j] = fmaf(ra[i], rb[j], acc[i][j]);
        }
        __syncthreads();
    }

    #pragma unroll
    for (int i = 0; i < 8; i++) {
        long row = (long)(bm + ty * 8 + i) * N + bn + tx * 8;
        *(float4*)&C[row]     = make_float4(acc[i][0], acc[i][1], acc[i][2], acc[i][3]);
        *(float4*)&C[row + 4] = make_float4(acc[i][4], acc[i][5], acc[i][6], acc[i][7]);
    }
}

// ---------------------------------------------------------------------------
// Flash attention (causal), fp32. One CTA per (q-tile of 64, head, batch).
// Smem: Qt[64][68] (d-major), Kt[64][68] (d-major), Vs[64][68], Ps[64][68].
// ---------------------------------------------------------------------------
#define PSTR 68
#define TILE_FLOATS (64 * PSTR)

__global__ __launch_bounds__(256) void flash_attn(
    const float* __restrict__ Qg, const float* __restrict__ Kg,
    const float* __restrict__ Vg, float* __restrict__ Og)
{
    extern __shared__ float sm[];
    float* Qt = sm;                       // Qt[d*68 + r]
    float* Kt = sm + TILE_FLOATS;         // Kt[d*68 + c]
    float* Vs = sm + 2 * TILE_FLOATS;     // Vs[k*68 + c]
    float* Ps = sm + 3 * TILE_FLOATS;     // Ps[r*68 + k]

    const int tid = threadIdx.x;
    const int qt = blockIdx.x, h = blockIdx.y, b = blockIdx.z;

    const long baseQ = ((long)(b * SEQ + qt * 64)) * DMOD + h * 64;

    // Load Q tile transposed: Qt[d][r]
    for (int i = tid; i < 64 * 64; i += 256) {
        int r = i >> 6, d = i & 63;
        Qt[d * PSTR + r] = Qg[baseQ + (long)r * DMOD + d];
    }

    // Per-thread softmax / output state: thread handles row r, cols quad*16..+15
    const int r    = tid >> 2;
    const int quad = tid & 3;
    float mrow = -1e30f, lrow = 0.f;
    float acc[16];
    #pragma unroll
    for (int c = 0; c < 16; c++) acc[c] = 0.f;

    // Phase-A micro-tile: 4x4 scores per thread
    const int tr = (tid >> 4) * 4;   // 0..60
    const int tc = (tid & 15) * 4;   // 0..60
    const float scaling = 0.125f;    // 1/sqrt(64)

    for (int kt = 0; kt <= qt; kt++) {
        __syncthreads();   // protect Kt/Vs (prev phase C) before overwrite
        const long baseK = ((long)(b * SEQ + kt * 64)) * DMOD + h * 64;
        for (int i = tid; i < 64 * 64; i += 256) {
            int kc = i >> 6, d = i & 63;
            Kt[d * PSTR + kc] = Kg[baseK + (long)kc * DMOD + d];
        }
        for (int i = tid; i < 64 * 64; i += 256) {
            int k = i >> 6, c = i & 63;
            Vs[k * PSTR + c] = Vg[baseK + (long)k * DMOD + c];
        }
        __syncthreads();

        // ---- Phase A: S = Q K^T (4x4 per thread) ----
        float s[4][4];
        #pragma unroll
        for (int i = 0; i < 4; i++)
            #pragma unroll
            for (int j = 0; j < 4; j++) s[i][j] = 0.f;

        #pragma unroll 8
        for (int d = 0; d < 64; d++) {
            float4 q4 = *(const float4*)&Qt[d * PSTR + tr];
            float4 k4 = *(const float4*)&Kt[d * PSTR + tc];
            float qa[4] = {q4.x, q4.y, q4.z, q4.w};
            float kb[4] = {k4.x, k4.y, k4.z, k4.w};
            #pragma unroll
            for (int i = 0; i < 4; i++)
                #pragma unroll
                for (int j = 0; j < 4; j++)
                    s[i][j] = fmaf(qa[i], kb[j], s[i][j]);
        }

        // scale + causal mask, store to Ps
        const int gq0 = qt * 64 + tr, gk0 = kt * 64 + tc;
        #pragma unroll
        for (int i = 0; i < 4; i++) {
            float4 v;
            v.x = (gk0 + 0 > gq0 + i) ? -1e30f : s[i][0] * scaling;
            v.y = (gk0 + 1 > gq0 + i) ? -1e30f : s[i][1] * scaling;
            v.z = (gk0 + 2 > gq0 + i) ? -1e30f : s[i][2] * scaling;
            v.w = (gk0 + 3 > gq0 + i) ? -1e30f : s[i][3] * scaling;
            *(float4*)&Ps[(tr + i) * PSTR + tc] = v;
        }
        __syncthreads();

        // ---- Phase B: online softmax on own 16-col segment of row r ----
        float sv[16];
        #pragma unroll
        for (int u = 0; u < 4; u++) {
            float4 t = *(const float4*)&Ps[r * PSTR + quad * 16 + u * 4];
            sv[u * 4 + 0] = t.x; sv[u * 4 + 1] = t.y;
            sv[u * 4 + 2] = t.z; sv[u * 4 + 3] = t.w;
        }
        float mloc = sv[0];
        #pragma unroll
        for (int i = 1; i < 16; i++) mloc = fmaxf(mloc, sv[i]);
        mloc = fmaxf(mloc, __shfl_xor_sync(0xffffffffu, mloc, 1));
        mloc = fmaxf(mloc, __shfl_xor_sync(0xffffffffu, mloc, 2));
        float mnew  = fmaxf(mrow, mloc);
        float alpha = __expf(mrow - mnew);
        float lsum = 0.f;
        #pragma unroll
        for (int i = 0; i < 16; i++) {
            sv[i] = __expf(sv[i] - mnew);
            lsum += sv[i];
        }
        #pragma unroll
        for (int u = 0; u < 4; u++) {
            float4 t = make_float4(sv[u*4+0], sv[u*4+1], sv[u*4+2], sv[u*4+3]);
            *(float4*)&Ps[r * PSTR + quad * 16 + u * 4] = t;
        }
        lsum += __shfl_xor_sync(0xffffffffu, lsum, 1);
        lsum += __shfl_xor_sync(0xffffffffu, lsum, 2);
        lrow = lrow * alpha + lsum;
        mrow = mnew;
        #pragma unroll
        for (int c = 0; c < 16; c++) acc[c] *= alpha;
        __syncthreads();

        // ---- Phase C: acc += P[r,:] @ V[:, quad*16..] ----
        #pragma unroll 8
        for (int k = 0; k < 64; k++) {
            float p = Ps[r * PSTR + k];
            const float* vrow = &Vs[k * PSTR + quad * 16];
            float4 v0 = *(const float4*)&vrow[0];
            float4 v1 = *(const float4*)&vrow[4];
            float4 v2 = *(const float4*)&vrow[8];
            float4 v3 = *(const float4*)&vrow[12];
            acc[0]  = fmaf(p, v0.x, acc[0]);  acc[1]  = fmaf(p, v0.y, acc[1]);
            acc[2]  = fmaf(p, v0.z, acc[2]);  acc[3]  = fmaf(p, v0.w, acc[3]);
            acc[4]  = fmaf(p, v1.x, acc[4]);  acc[5]  = fmaf(p, v1.y, acc[5]);
            acc[6]  = fmaf(p, v1.z, acc[6]);  acc[7]  = fmaf(p, v1.w, acc[7]);
            acc[8]  = fmaf(p, v2.x, acc[8]);  acc[9]  = fmaf(p, v2.y, acc[9]);
            acc[10] = fmaf(p, v2.z, acc[10]); acc[11] = fmaf(p, v2.w, acc[11]);
            acc[12] = fmaf(p, v3.x, acc[12]); acc[13] = fmaf(p, v3.y, acc[13]);
            acc[14] = fmaf(p, v3.z, acc[14]); acc[15] = fmaf(p, v3.w, acc[15]);
        }
    }

    // Write output row segment
    float inv = 1.f / lrow;
    long baseO = ((long)(b * SEQ + qt * 64 + r)) * DMOD + h * 64 + quad * 16;
    #pragma unroll
    for (int u = 0; u < 4; u++) {
        float4 t = make_float4(acc[u*4+0]*inv, acc[u*4+1]*inv,
                               acc[u*4+2]*inv, acc[u*4+3]*inv);
        *(float4*)&Og[baseO + u * 4] = t;
    }
}

// ---------------------------------------------------------------------------
// Host launcher
// ---------------------------------------------------------------------------
extern "C" void kernel_launch(void* const* d_in, const int* in_sizes, int n_in,
                              void* d_out, int out_size)
{
    const float* queries = (const float*)d_in[0];
    const float* keys    = (const float*)d_in[1];
    const float* values  = (const float*)d_in[2];
    // d_in[3] = mask (int32) — causal, implemented analytically
    const float* W_Q = (const float*)d_in[4];
    const float* W_K = (const float*)d_in[5];
    const float* W_V = (const float*)d_in[6];
    const float* W_O = (const float*)d_in[7];
    float* out = (float*)d_out;

    float *Qb, *Kb, *Vb, *Ab;
    cudaGetSymbolAddress((void**)&Qb, g_Q);
    cudaGetSymbolAddress((void**)&Kb, g_K);
    cudaGetSymbolAddress((void**)&Vb, g_V);
    cudaGetSymbolAddress((void**)&Ab, g_A);

    const int smem_bytes = 4 * TILE_FLOATS * sizeof(float);  // ~69.6 KB
    cudaFuncSetAttribute(flash_attn, cudaFuncAttributeMaxDynamicSharedMemorySize,
                         smem_bytes);

    dim3 ggrid(DMOD / 128, MROWS / 128);   // (8, 64)
    sgemm128<<<ggrid, 256>>>(queries, W_Q, Qb, MROWS, DMOD, DMOD);
    sgemm128<<<ggrid, 256>>>(keys,    W_K, Kb, MROWS, DMOD, DMOD);
    sgemm128<<<ggrid, 256>>>(values,  W_V, Vb, MROWS, DMOD, DMOD);

    dim3 agrid(SEQ / 64, NHEAD, BATCH);    // (32, 16, 4)
    flash_attn<<<agrid, 256, smem_bytes>>>(Qb, Kb, Vb, Ab);

    sgemm128<<<ggrid, 256>>>(Ab, W_O, out, MROWS, DMOD, DMOD);
}

// round 3
// speedup vs baseline: 1.4287x; 1.4287x over previous
#include <cuda_runtime.h>
#include <cuda.h>
#include <math.h>
#include <stdint.h>

// Problem dims (fixed)
#define BATCH 4
#define SEQ   2048
#define DMOD  1024
#define NHEAD 16
#define HDIM  64
#define MROWS (BATCH*SEQ)   // 8192

// Scratch (device globals; no allocation allowed)
__device__ float g_Q[BATCH*SEQ*DMOD];
__device__ float g_K[BATCH*SEQ*DMOD];
__device__ float g_V[BATCH*SEQ*DMOD];
__device__ float g_A[BATCH*SEQ*DMOD];
__device__ float g_Wt[DMOD*DMOD];      // transposed (and tf32-rounded) weight

// tcgen05 only exists in the arch-SPECIFIC (sm_103a) compilation pass.
// Any generic pass (compute_103 / sm_103) gets a SIMT fallback body.
#if defined(__CUDA_ARCH_FEAT_SM103_ALL) || \
    (defined(__CUDA_ARCH_SPECIFIC__) && (__CUDA_ARCH_SPECIFIC__ == 1030)) || \
    defined(__CUDA_ARCH_FEAT_SM100_ALL)
#define USE_TC 1
#else
#define USE_TC 0
#endif

// ---------------------------------------------------------------------------
// Helpers
// ---------------------------------------------------------------------------
__device__ __forceinline__ float cvt_tf32(float x) {
    uint32_t u;
    asm("cvt.rna.tf32.f32 %0, %1;" : "=r"(u) : "f"(x));
    return __uint_as_float(u);
}

#if USE_TC
__device__ __forceinline__ uint32_t smem_u32(const void* p) {
    uint32_t a;
    asm("{ .reg .u64 t; cvta.to.shared.u64 t, %1; cvt.u32.u64 %0, t; }"
        : "=r"(a) : "l"(p));
    return a;
}
__device__ __forceinline__ uint32_t elect_one() {
    uint32_t pred;
    asm volatile("{\n\t.reg .pred p;\n\telect.sync _|p, 0xFFFFFFFF;\n\t"
                 "selp.b32 %0, 1, 0, p;\n\t}" : "=r"(pred));
    return pred;
}

#define MBAR_INIT(a, n) \
    asm volatile("mbarrier.init.shared.b64 [%0], %1;" :: "r"(a), "r"(n) : "memory")
#define MBAR_INVAL(a) \
    asm volatile("mbarrier.inval.shared.b64 [%0];" :: "r"(a) : "memory")
#define MBAR_WAIT(a, ph) do {                                                  \
    uint32_t _m = (a), _p = (ph), _d;                                          \
    asm volatile("{\n\t.reg .pred p;\n\t"                                      \
        "mbarrier.try_wait.parity.acquire.cta.shared::cta.b64 p, [%1], %2;\n\t"\
        "selp.b32 %0, 1, 0, p;\n\t}" : "=r"(_d) : "r"(_m), "r"(_p) : "memory");\
    if (!_d) {                                                                 \
        asm volatile("{\n\t.reg .pred P1;\n\tWL_%=:\n\t"                       \
            "mbarrier.try_wait.parity.acquire.cta.shared::cta.b64 P1, [%0], %1, 0x989680;\n\t" \
            "@P1 bra.uni WD_%=;\n\tbra.uni WL_%=;\n\tWD_%=:\n\t}"              \
            :: "r"(_m), "r"(_p) : "memory");                                   \
    }                                                                          \
} while (0)

#define TC_ALLOC(smem_addr, n) \
    asm volatile("tcgen05.alloc.cta_group::1.sync.aligned.shared::cta.b32 [%0], %1;" \
        :: "r"(smem_addr), "r"((uint32_t)(n)) : "memory")
#define TC_DEALLOC(tmem, n) \
    asm volatile("tcgen05.dealloc.cta_group::1.sync.aligned.b32 %0, %1;" \
        :: "r"(tmem), "r"((uint32_t)(n)))
#define TC_RELINQ() \
    asm volatile("tcgen05.relinquish_alloc_permit.cta_group::1.sync.aligned;")
#define TC_COMMIT(mbar) \
    asm volatile("tcgen05.commit.cta_group::1.mbarrier::arrive::one.shared::cluster.b64 [%0];" \
        :: "r"(mbar) : "memory")
#define TC_FENCE_AFTER()  asm volatile("tcgen05.fence::after_thread_sync;" ::: "memory")
#define TC_FENCE_BEFORE() asm volatile("tcgen05.fence::before_thread_sync;" ::: "memory")
#define FENCE_ASYNC_SHARED() asm volatile("fence.proxy.async.shared::cta;" ::: "memory")
#define TC_WAIT_LD() asm volatile("tcgen05.wait::ld.sync.aligned;" ::: "memory")

#define TC_LD_X32(r, tmem) \
    asm volatile("tcgen05.ld.sync.aligned.32x32b.x32.b32 " \
        "{%0,%1,%2,%3,%4,%5,%6,%7,%8,%9,%10,%11,%12,%13,%14,%15," \
        "%16,%17,%18,%19,%20,%21,%22,%23,%24,%25,%26,%27,%28,%29,%30,%31}, [%32];" \
        : "=r"((r)[0]),"=r"((r)[1]),"=r"((r)[2]),"=r"((r)[3]), \
          "=r"((r)[4]),"=r"((r)[5]),"=r"((r)[6]),"=r"((r)[7]), \
          "=r"((r)[8]),"=r"((r)[9]),"=r"((r)[10]),"=r"((r)[11]), \
          "=r"((r)[12]),"=r"((r)[13]),"=r"((r)[14]),"=r"((r)[15]), \
          "=r"((r)[16]),"=r"((r)[17]),"=r"((r)[18]),"=r"((r)[19]), \
          "=r"((r)[20]),"=r"((r)[21]),"=r"((r)[22]),"=r"((r)[23]), \
          "=r"((r)[24]),"=r"((r)[25]),"=r"((r)[26]),"=r"((r)[27]), \
          "=r"((r)[28]),"=r"((r)[29]),"=r"((r)[30]),"=r"((r)[31]) \
        : "r"(tmem))

// SMEM descriptor: SW128, Blackwell, LBO=1, SBO=64 (K-major)
static __device__ __forceinline__ uint64_t make_desc(uint32_t addr) {
    const uint64_t base =
        (uint64_t(2) << 61) | (uint64_t(1) << 46) | (uint64_t(64) << 32) | (uint64_t(1) << 16);
    return base | ((uint64_t)(addr >> 4) & 0x3FFF);
}

__device__ __forceinline__ void mma_tf32_ss(
    uint32_t d, uint64_t ad, uint64_t bd, uint32_t idesc, uint32_t en)
{
    asm volatile("{\n\t.reg .pred p;\n\tsetp.ne.u32 p, %5, 0;\n\t"
        "tcgen05.mma.cta_group::1.kind::tf32 [%0], %1, %2, %3, {%4,%4,%4,%4}, p;\n\t}"
        :: "r"(d), "l"(ad), "l"(bd), "r"(idesc), "r"(0u), "r"(en) : "memory");
}
// idesc: dtype=F32(1<<4), atype=btype=TF32(2<<7 / 2<<10), N=128 (16<<17), M=128 (8<<24)
#define IDESC_TF32 0x8200910u
#endif  // USE_TC

// ---------------------------------------------------------------------------
// GEMM: C[M,1024] = A[M,1024] @ Bt^T  (Bt is [N,K]=[1024,1024], K-major)
// sm_103a pass: tcgen05 tf32, 128x128 tile, K-chunk 32 floats, double buffered.
// generic pass: SIMT fp32 fallback (8x8 micro-tiles).
// ---------------------------------------------------------------------------
#define GK        1024
#define KCHUNK    32
#define NCHUNK    (GK / KCHUNK)            // 32
#define TILE_B    (128 * 128)              // bytes per stage tile
#define SM_HDR    1024
#define SM_A(s)   (SM_HDR + (s) * TILE_B)
#define SM_B(s)   (SM_HDR + 2 * TILE_B + (s) * TILE_B)
#define GEMM_SMEM (SM_HDR + 4 * TILE_B)    // 66560 bytes

#if USE_TC
__device__ __forceinline__ void load_tile(
    char* smem, int stage, const float* __restrict__ A, const float* __restrict__ Bt,
    long bm, long bn, int k0, int tid)
{
    const int r  = tid >> 3;           // 0..31
    const int kk = (tid & 7) * 4;      // 0..28
    char* sA = smem + SM_A(stage);
    char* sB = smem + SM_B(stage);
    #pragma unroll
    for (int p = 0; p < 4; p++) {
        int row = p * 32 + r;
        float4 a = *(const float4*)&A [(bm + row) * (long)GK + k0 + kk];
        float4 b = *(const float4*)&Bt[(bn + row) * (long)GK + k0 + kk];
        uint32_t off = (uint32_t)(row * 128 + kk * 4);
        uint32_t sw  = off ^ ((off >> 3) & 0x70);
        float4 ac = make_float4(cvt_tf32(a.x), cvt_tf32(a.y), cvt_tf32(a.z), cvt_tf32(a.w));
        float4 bc = make_float4(cvt_tf32(b.x), cvt_tf32(b.y), cvt_tf32(b.z), cvt_tf32(b.w));
        *(float4*)(sA + sw) = ac;
        *(float4*)(sB + sw) = bc;
    }
}
#endif

__global__ __launch_bounds__(256)
void gemm_tn(const float* __restrict__ A, const float* __restrict__ Bt,
             float* __restrict__ C)
{
    extern __shared__ char smem[];
    const int tid = threadIdx.x;
    const long bm = (long)blockIdx.y * 128;
    const long bn = (long)blockIdx.x * 128;

#if USE_TC
    const uint32_t smem_base = smem_u32(smem);
    const int wid = tid >> 5;
    const int lid = tid & 31;
    const uint32_t mb0 = smem_base + 8;
    const uint32_t mb1 = smem_base + 16;

    if (wid == 0) {
        TC_ALLOC(smem_base, 128);
        TC_RELINQ();
    }
    if (tid == 0) { MBAR_INIT(mb0, 1); MBAR_INIT(mb1, 1); }
    __syncthreads();
    uint32_t tmem;
    asm volatile("ld.shared.b32 %0, [%1];" : "=r"(tmem) : "r"(smem_base));

    load_tile(smem, 0, A, Bt, bm, bn, 0, tid);
    uint32_t ph[2] = {0, 0};

    for (int c = 0; c < NCHUNK; c++) {
        const int s = c & 1;
        __syncthreads();

        if (wid == 0 && elect_one()) {
            FENCE_ASYNC_SHARED();
            uint64_t ad = make_desc(smem_base + SM_A(s));
            uint64_t bd = make_desc(smem_base + SM_B(s));
            #pragma unroll
            for (int k = 0; k < 4; k++)   // 4 x (K=8) tf32 MMAs per 32-float chunk
                mma_tf32_ss(tmem, ad + k * 2, bd + k * 2, IDESC_TF32,
                            (c > 0) | (k > 0));
            TC_COMMIT(s ? mb1 : mb0);
        }

        if (c + 1 < NCHUNK) {
            const int ns = (c + 1) & 1;
            if (c >= 1) {
                MBAR_WAIT(ns ? mb1 : mb0, ph[ns]);
                ph[ns] ^= 1;
            }
            load_tile(smem, ns, A, Bt, bm, bn, (c + 1) * KCHUNK, tid);
        }
    }
    {
        const int ls = (NCHUNK - 1) & 1;
        MBAR_WAIT(ls ? mb1 : mb0, ph[ls]);
        ph[ls] ^= 1;
    }
    TC_FENCE_AFTER();

    if (wid < 4) {
        const long row = bm + wid * 32 + lid;
        float* crow = &C[row * (long)GK + bn];
        #pragma unroll
        for (int nb = 0; nb < 4; nb++) {
            uint32_t r[32];
            TC_LD_X32(r, tmem + nb * 32);
            TC_WAIT_LD();
            #pragma unroll
            for (int j = 0; j < 8; j++) {
                float4 v = make_float4(__uint_as_float(r[j*4+0]), __uint_as_float(r[j*4+1]),
                                       __uint_as_float(r[j*4+2]), __uint_as_float(r[j*4+3]));
                *(float4*)&crow[nb * 32 + j * 4] = v;
            }
        }
        TC_FENCE_BEFORE();
    }
    __syncthreads();
    if (tid == 0) { MBAR_INVAL(mb0); MBAR_INVAL(mb1); }
    if (wid == 0) TC_DEALLOC(tmem, 128);

#else  // ---------------- SIMT fallback (generic pass) ----------------
    float* As = (float*)smem;              // As[k][m], 16x128
    float* Bs = (float*)smem + 16 * 128;   // Bs[k][n], 16x128

    const int tx = tid & 15;
    const int ty = tid >> 4;
    const int ar = tid >> 2;               // 0..63
    const int ak = (tid & 3) * 4;

    float acc[8][8];
    #pragma unroll
    for (int i = 0; i < 8; i++)
        #pragma unroll
        for (int j = 0; j < 8; j++) acc[i][j] = 0.f;

    for (int k0 = 0; k0 < GK; k0 += 16) {
        float4 a0 = *(const float4*)&A [(bm + ar)      * (long)GK + k0 + ak];
        float4 a1 = *(const float4*)&A [(bm + ar + 64) * (long)GK + k0 + ak];
        float4 b0 = *(const float4*)&Bt[(bn + ar)      * (long)GK + k0 + ak];
        float4 b1 = *(const float4*)&Bt[(bn + ar + 64) * (long)GK + k0 + ak];

        As[(ak + 0) * 128 + ar] = a0.x;  As[(ak + 1) * 128 + ar] = a0.y;
        As[(ak + 2) * 128 + ar] = a0.z;  As[(ak + 3) * 128 + ar] = a0.w;
        As[(ak + 0) * 128 + ar + 64] = a1.x;  As[(ak + 1) * 128 + ar + 64] = a1.y;
        As[(ak + 2) * 128 + ar + 64] = a1.z;  As[(ak + 3) * 128 + ar + 64] = a1.w;
        Bs[(ak + 0) * 128 + ar] = b0.x;  Bs[(ak + 1) * 128 + ar] = b0.y;
        Bs[(ak + 2) * 128 + ar] = b0.z;  Bs[(ak + 3) * 128 + ar] = b0.w;
        Bs[(ak + 0) * 128 + ar + 64] = b1.x;  Bs[(ak + 1) * 128 + ar + 64] = b1.y;
        Bs[(ak + 2) * 128 + ar + 64] = b1.z;  Bs[(ak + 3) * 128 + ar + 64] = b1.w;
        __syncthreads();

        #pragma unroll
        for (int kk = 0; kk < 16; kk++) {
            float ra[8], rb[8];
            *(float4*)&ra[0] = *(const float4*)&As[kk * 128 + ty * 8];
            *(float4*)&ra[4] = *(const float4*)&As[kk * 128 + ty * 8 + 4];
            *(float4*)&rb[0] = *(const float4*)&Bs[kk * 128 + tx * 8];
            *(float4*)&rb[4] = *(const float4*)&Bs[kk * 128 + tx * 8 + 4];
            #pragma unroll
            for (int i = 0; i < 8; i++)
                #pragma unroll
                for (int j = 0; j < 8; j++)
                    acc[i][j] = fmaf(ra[i], rb[j], acc[i][j]);
        }
        __syncthreads();
    }

    #pragma unroll
    for (int i = 0; i < 8; i++) {
        long row = (bm + ty * 8 + i) * (long)GK + bn + tx * 8;
        *(float4*)&C[row]     = make_float4(acc[i][0], acc[i][1], acc[i][2], acc[i][3]);
        *(float4*)&C[row + 4] = make_float4(acc[i][4], acc[i][5], acc[i][6], acc[i][7]);
    }
#endif
}

// ---------------------------------------------------------------------------
// Transpose + tf32-round weights: Wt[n][k] = rna_tf32(W[k][n])
// ---------------------------------------------------------------------------
__global__ __launch_bounds__(256) void transpose_cvt(
    const float* __restrict__ W, float* __restrict__ Wt)
{
    __shared__ float t[32][33];
    const int tx = threadIdx.x, ty = threadIdx.y;  // 32 x 8
    const int n0 = blockIdx.x * 32, k0 = blockIdx.y * 32;
    #pragma unroll
    for (int i = 0; i < 4; i++)
        t[ty + 8 * i][tx] = W[(long)(k0 + ty + 8 * i) * DMOD + n0 + tx];
    __syncthreads();
    #pragma unroll
    for (int i = 0; i < 4; i++)
        Wt[(long)(n0 + ty + 8 * i) * DMOD + k0 + tx] = cvt_tf32(t[tx][ty + 8 * i]);
}

// ---------------------------------------------------------------------------
// Flash attention (causal), fp32 — unchanged
// ---------------------------------------------------------------------------
#define PSTR 68
#define TILE_FLOATS (64 * PSTR)

__global__ __launch_bounds__(256) void flash_attn(
    const float* __restrict__ Qg, const float* __restrict__ Kg,
    const float* __restrict__ Vg, float* __restrict__ Og)
{
    extern __shared__ float sm[];
    float* Qt = sm;
    float* Kt = sm + TILE_FLOATS;
    float* Vs = sm + 2 * TILE_FLOATS;
    float* Ps = sm + 3 * TILE_FLOATS;

    const int tid = threadIdx.x;
    const int qt = blockIdx.x, h = blockIdx.y, b = blockIdx.z;
    const long baseQ = ((long)(b * SEQ + qt * 64)) * DMOD + h * 64;

    for (int i = tid; i < 64 * 64; i += 256) {
        int r = i >> 6, d = i & 63;
        Qt[d * PSTR + r] = Qg[baseQ + (long)r * DMOD + d];
    }

    const int r    = tid >> 2;
    const int quad = tid & 3;
    float mrow = -1e30f, lrow = 0.f;
    float acc[16];
    #pragma unroll
    for (int c = 0; c < 16; c++) acc[c] = 0.f;

    const int tr = (tid >> 4) * 4;
    const int tc = (tid & 15) * 4;
    const float scaling = 0.125f;

    for (int kt = 0; kt <= qt; kt++) {
        __syncthreads();
        const long baseK = ((long)(b * SEQ + kt * 64)) * DMOD + h * 64;
        for (int i = tid; i < 64 * 64; i += 256) {
            int kc = i >> 6, d = i & 63;
            Kt[d * PSTR + kc] = Kg[baseK + (long)kc * DMOD + d];
        }
        for (int i = tid; i < 64 * 64; i += 256) {
            int k = i >> 6, c = i & 63;
            Vs[k * PSTR + c] = Vg[baseK + (long)k * DMOD + c];
        }
        __syncthreads();

        float s[4][4];
        #pragma unroll
        for (int i = 0; i < 4; i++)
            #pragma unroll
            for (int j = 0; j < 4; j++) s[i][j] = 0.f;

        #pragma unroll 8
        for (int d = 0; d < 64; d++) {
            float4 q4 = *(const float4*)&Qt[d * PSTR + tr];
            float4 k4 = *(const float4*)&Kt[d * PSTR + tc];
            float qa[4] = {q4.x, q4.y, q4.z, q4.w};
            float kb[4] = {k4.x, k4.y, k4.z, k4.w};
            #pragma unroll
            for (int i = 0; i < 4; i++)
                #pragma unroll
                for (int j = 0; j < 4; j++)
                    s[i][j] = fmaf(qa[i], kb[j], s[i][j]);
        }

        const int gq0 = qt * 64 + tr, gk0 = kt * 64 + tc;
        #pragma unroll
        for (int i = 0; i < 4; i++) {
            float4 v;
            v.x = (gk0 + 0 > gq0 + i) ? -1e30f : s[i][0] * scaling;
            v.y = (gk0 + 1 > gq0 + i) ? -1e30f : s[i][1] * scaling;
            v.z = (gk0 + 2 > gq0 + i) ? -1e30f : s[i][2] * scaling;
            v.w = (gk0 + 3 > gq0 + i) ? -1e30f : s[i][3] * scaling;
            *(float4*)&Ps[(tr + i) * PSTR + tc] = v;
        }
        __syncthreads();

        float sv[16];
        #pragma unroll
        for (int u = 0; u < 4; u++) {
            float4 t = *(const float4*)&Ps[r * PSTR + quad * 16 + u * 4];
            sv[u * 4 + 0] = t.x; sv[u * 4 + 1] = t.y;
            sv[u * 4 + 2] = t.z; sv[u * 4 + 3] = t.w;
        }
        float mloc = sv[0];
        #pragma unroll
        for (int i = 1; i < 16; i++) mloc = fmaxf(mloc, sv[i]);
        mloc = fmaxf(mloc, __shfl_xor_sync(0xffffffffu, mloc, 1));
        mloc = fmaxf(mloc, __shfl_xor_sync(0xffffffffu, mloc, 2));
        float mnew  = fmaxf(mrow, mloc);
        float alpha = __expf(mrow - mnew);
        float lsum = 0.f;
        #pragma unroll
        for (int i = 0; i < 16; i++) {
            sv[i] = __expf(sv[i] - mnew);
            lsum += sv[i];
        }
        #pragma unroll
        for (int u = 0; u < 4; u++) {
            float4 t = make_float4(sv[u*4+0], sv[u*4+1], sv[u*4+2], sv[u*4+3]);
            *(float4*)&Ps[r * PSTR + quad * 16 + u * 4] = t;
        }
        lsum += __shfl_xor_sync(0xffffffffu, lsum, 1);
        lsum += __shfl_xor_sync(0xffffffffu, lsum, 2);
        lrow = lrow * alpha + lsum;
        mrow = mnew;
        #pragma unroll
        for (int c = 0; c < 16; c++) acc[c] *= alpha;
        __syncthreads();

        #pragma unroll 8
        for (int k = 0; k < 64; k++) {
            float p = Ps[r * PSTR + k];
            const float* vrow = &Vs[k * PSTR + quad * 16];
            float4 v0 = *(const float4*)&vrow[0];
            float4 v1 = *(const float4*)&vrow[4];
            float4 v2 = *(const float4*)&vrow[8];
            float4 v3 = *(const float4*)&vrow[12];
            acc[0]  = fmaf(p, v0.x, acc[0]);  acc[1]  = fmaf(p, v0.y, acc[1]);
            acc[2]  = fmaf(p, v0.z, acc[2]);  acc[3]  = fmaf(p, v0.w, acc[3]);
            acc[4]  = fmaf(p, v1.x, acc[4]);  acc[5]  = fmaf(p, v1.y, acc[5]);
            acc[6]  = fmaf(p, v1.z, acc[6]);  acc[7]  = fmaf(p, v1.w, acc[7]);
            acc[8]  = fmaf(p, v2.x, acc[8]);  acc[9]  = fmaf(p, v2.y, acc[9]);
            acc[10] = fmaf(p, v2.z, acc[10]); acc[11] = fmaf(p, v2.w, acc[11]);
            acc[12] = fmaf(p, v3.x, acc[12]); acc[13] = fmaf(p, v3.y, acc[13]);
            acc[14] = fmaf(p, v3.z, acc[14]); acc[15] = fmaf(p, v3.w, acc[15]);
        }
    }

    float inv = 1.f / lrow;
    long baseO = ((long)(b * SEQ + qt * 64 + r)) * DMOD + h * 64 + quad * 16;
    #pragma unroll
    for (int u = 0; u < 4; u++) {
        float4 t = make_float4(acc[u*4+0]*inv, acc[u*4+1]*inv,
                               acc[u*4+2]*inv, acc[u*4+3]*inv);
        *(float4*)&Og[baseO + u * 4] = t;
    }
}

// ---------------------------------------------------------------------------
// Host launcher
// ---------------------------------------------------------------------------
extern "C" void kernel_launch(void* const* d_in, const int* in_sizes, int n_in,
                              void* d_out, int out_size)
{
    const float* queries = (const float*)d_in[0];
    const float* keys    = (const float*)d_in[1];
    const float* values  = (const float*)d_in[2];
    // d_in[3] = mask (int32) — causal, analytic
    const float* W_Q = (const float*)d_in[4];
    const float* W_K = (const float*)d_in[5];
    const float* W_V = (const float*)d_in[6];
    const float* W_O = (const float*)d_in[7];
    float* out = (float*)d_out;

    float *Qb, *Kb, *Vb, *Ab, *Wt;
    cudaGetSymbolAddress((void**)&Qb, g_Q);
    cudaGetSymbolAddress((void**)&Kb, g_K);
    cudaGetSymbolAddress((void**)&Vb, g_V);
    cudaGetSymbolAddress((void**)&Ab, g_A);
    cudaGetSymbolAddress((void**)&Wt, g_Wt);

    cudaFuncSetAttribute(gemm_tn, cudaFuncAttributeMaxDynamicSharedMemorySize,
                         GEMM_SMEM);
    const int attn_smem = 4 * TILE_FLOATS * sizeof(float);
    cudaFuncSetAttribute(flash_attn, cudaFuncAttributeMaxDynamicSharedMemorySize,
                         attn_smem);

    dim3 tgrid(32, 32), tblk(32, 8);
    dim3 ggrid(DMOD / 128, MROWS / 128);   // (8, 64)

    transpose_cvt<<<tgrid, tblk>>>(W_Q, Wt);
    gemm_tn<<<ggrid, 256, GEMM_SMEM>>>(queries, Wt, Qb);

    transpose_cvt<<<tgrid, tblk>>>(W_K, Wt);
    gemm_tn<<<ggrid, 256, GEMM_SMEM>>>(keys, Wt, Kb);

    transpose_cvt<<<tgrid, tblk>>>(W_V, Wt);
    gemm_tn<<<ggrid, 256, GEMM_SMEM>>>(values, Wt, Vb);

    dim3 agrid(SEQ / 64, NHEAD, BATCH);
    flash_attn<<<agrid, 256, attn_smem>>>(Qb, Kb, Vb, Ab);

    transpose_cvt<<<tgrid, tblk>>>(W_O, Wt);
    gemm_tn<<<ggrid, 256, GEMM_SMEM>>>(Ab, Wt, out);
}

// round 4
// speedup vs baseline: 6.9046x; 4.8329x over previous
#include <cuda_runtime.h>
#include <cuda.h>
#include <math.h>
#include <stdint.h>

// Problem dims (fixed)
#define BATCH 4
#define SEQ   2048
#define DMOD  1024
#define NHEAD 16
#define HDIM  64
#define MROWS (BATCH*SEQ)   // 8192

// Scratch (device globals; no allocation allowed)
__device__ float g_Q[BATCH*SEQ*DMOD];
__device__ float g_K[BATCH*SEQ*DMOD];
__device__ float g_V[BATCH*SEQ*DMOD];
__device__ float g_A[BATCH*SEQ*DMOD];
__device__ float g_Wt[DMOD*DMOD];

// tcgen05 only exists in the arch-SPECIFIC (sm_103a) compilation pass.
#if defined(__CUDA_ARCH_FEAT_SM103_ALL) || \
    (defined(__CUDA_ARCH_SPECIFIC__) && (__CUDA_ARCH_SPECIFIC__ == 1030)) || \
    defined(__CUDA_ARCH_FEAT_SM100_ALL)
#define USE_TC 1
#else
#define USE_TC 0
#endif

// ---------------------------------------------------------------------------
// Helpers
// ---------------------------------------------------------------------------
__device__ __forceinline__ float cvt_tf32(float x) {
    uint32_t u;
    asm("cvt.rna.tf32.f32 %0, %1;" : "=r"(u) : "f"(x));
    return __uint_as_float(u);
}

#if USE_TC
__device__ __forceinline__ uint32_t smem_u32(const void* p) {
    uint32_t a;
    asm("{ .reg .u64 t; cvta.to.shared.u64 t, %1; cvt.u32.u64 %0, t; }"
        : "=r"(a) : "l"(p));
    return a;
}
__device__ __forceinline__ uint32_t elect_one() {
    uint32_t pred;
    asm volatile("{\n\t.reg .pred p;\n\telect.sync _|p, 0xFFFFFFFF;\n\t"
                 "selp.b32 %0, 1, 0, p;\n\t}" : "=r"(pred));
    return pred;
}

#define MBAR_INIT(a, n) \
    asm volatile("mbarrier.init.shared.b64 [%0], %1;" :: "r"(a), "r"(n) : "memory")
#define MBAR_INVAL(a) \
    asm volatile("mbarrier.inval.shared.b64 [%0];" :: "r"(a) : "memory")
#define MBAR_WAIT(a, ph) do {                                                  \
    uint32_t _m = (a), _p = (ph), _d;                                          \
    asm volatile("{\n\t.reg .pred p;\n\t"                                      \
        "mbarrier.try_wait.parity.acquire.cta.shared::cta.b64 p, [%1], %2;\n\t"\
        "selp.b32 %0, 1, 0, p;\n\t}" : "=r"(_d) : "r"(_m), "r"(_p) : "memory");\
    if (!_d) {                                                                 \
        asm volatile("{\n\t.reg .pred P1;\n\tWL_%=:\n\t"                       \
            "mbarrier.try_wait.parity.acquire.cta.shared::cta.b64 P1, [%0], %1, 0x989680;\n\t" \
            "@P1 bra.uni WD_%=;\n\tbra.uni WL_%=;\n\tWD_%=:\n\t}"              \
            :: "r"(_m), "r"(_p) : "memory");                                   \
    }                                                                          \
} while (0)

#define TC_ALLOC(smem_addr, n) \
    asm volatile("tcgen05.alloc.cta_group::1.sync.aligned.shared::cta.b32 [%0], %1;" \
        :: "r"(smem_addr), "r"((uint32_t)(n)) : "memory")
#define TC_DEALLOC(tmem, n) \
    asm volatile("tcgen05.dealloc.cta_group::1.sync.aligned.b32 %0, %1;" \
        :: "r"(tmem), "r"((uint32_t)(n)))
#define TC_RELINQ() \
    asm volatile("tcgen05.relinquish_alloc_permit.cta_group::1.sync.aligned;")
#define TC_COMMIT(mbar) \
    asm volatile("tcgen05.commit.cta_group::1.mbarrier::arrive::one.shared::cluster.b64 [%0];" \
        :: "r"(mbar) : "memory")
#define TC_FENCE_AFTER()  asm volatile("tcgen05.fence::after_thread_sync;" ::: "memory")
#define TC_FENCE_BEFORE() asm volatile("tcgen05.fence::before_thread_sync;" ::: "memory")
#define FENCE_ASYNC_SHARED() asm volatile("fence.proxy.async.shared::cta;" ::: "memory")
#define TC_WAIT_LD() asm volatile("tcgen05.wait::ld.sync.aligned;" ::: "memory")

#define TC_LD_X32(r, tmem) \
    asm volatile("tcgen05.ld.sync.aligned.32x32b.x32.b32 " \
        "{%0,%1,%2,%3,%4,%5,%6,%7,%8,%9,%10,%11,%12,%13,%14,%15," \
        "%16,%17,%18,%19,%20,%21,%22,%23,%24,%25,%26,%27,%28,%29,%30,%31}, [%32];" \
        : "=r"((r)[0]),"=r"((r)[1]),"=r"((r)[2]),"=r"((r)[3]), \
          "=r"((r)[4]),"=r"((r)[5]),"=r"((r)[6]),"=r"((r)[7]), \
          "=r"((r)[8]),"=r"((r)[9]),"=r"((r)[10]),"=r"((r)[11]), \
          "=r"((r)[12]),"=r"((r)[13]),"=r"((r)[14]),"=r"((r)[15]), \
          "=r"((r)[16]),"=r"((r)[17]),"=r"((r)[18]),"=r"((r)[19]), \
          "=r"((r)[20]),"=r"((r)[21]),"=r"((r)[22]),"=r"((r)[23]), \
          "=r"((r)[24]),"=r"((r)[25]),"=r"((r)[26]),"=r"((r)[27]), \
          "=r"((r)[28]),"=r"((r)[29]),"=r"((r)[30]),"=r"((r)[31]) \
        : "r"(tmem))

// SMEM descriptor: SW128, Blackwell, LBO=1, SBO=64 (K-major)
static __device__ __forceinline__ uint64_t make_desc(uint32_t addr) {
    const uint64_t base =
        (uint64_t(2) << 61) | (uint64_t(1) << 46) | (uint64_t(64) << 32) | (uint64_t(1) << 16);
    return base | ((uint64_t)(addr >> 4) & 0x3FFF);
}

__device__ __forceinline__ void mma_tf32_ss(
    uint32_t d, uint64_t ad, uint64_t bd, uint32_t idesc, uint32_t en)
{
    asm volatile("{\n\t.reg .pred p;\n\tsetp.ne.u32 p, %5, 0;\n\t"
        "tcgen05.mma.cta_group::1.kind::tf32 [%0], %1, %2, %3, {%4,%4,%4,%4}, p;\n\t}"
        :: "r"(d), "l"(ad), "l"(bd), "r"(idesc), "r"(0u), "r"(en) : "memory");
}
// dtype=F32, a/btype=TF32, M=128; N=128 / N=64 variants
#define IDESC_N128 0x8200910u
#define IDESC_N64  0x8100910u
#define IDESC_TF32 IDESC_N128
#endif  // USE_TC

// ---------------------------------------------------------------------------
// GEMM: C[M,1024] = A[M,1024] @ Bt^T  (Bt is [N,K], K-major)  — unchanged R3
// ---------------------------------------------------------------------------
#define GK        1024
#define KCHUNK    32
#define NCHUNK    (GK / KCHUNK)
#define TILE_B    (128 * 128)
#define SM_HDR    1024
#define SM_A(s)   (SM_HDR + (s) * TILE_B)
#define SM_B(s)   (SM_HDR + 2 * TILE_B + (s) * TILE_B)
#define GEMM_SMEM (SM_HDR + 4 * TILE_B)

#if USE_TC
__device__ __forceinline__ void load_tile(
    char* smem, int stage, const float* __restrict__ A, const float* __restrict__ Bt,
    long bm, long bn, int k0, int tid)
{
    const int r  = tid >> 3;
    const int kk = (tid & 7) * 4;
    char* sA = smem + SM_A(stage);
    char* sB = smem + SM_B(stage);
    #pragma unroll
    for (int p = 0; p < 4; p++) {
        int row = p * 32 + r;
        float4 a = *(const float4*)&A [(bm + row) * (long)GK + k0 + kk];
        float4 b = *(const float4*)&Bt[(bn + row) * (long)GK + k0 + kk];
        uint32_t off = (uint32_t)(row * 128 + kk * 4);
        uint32_t sw  = off ^ ((off >> 3) & 0x70);
        float4 ac = make_float4(cvt_tf32(a.x), cvt_tf32(a.y), cvt_tf32(a.z), cvt_tf32(a.w));
        float4 bc = make_float4(cvt_tf32(b.x), cvt_tf32(b.y), cvt_tf32(b.z), cvt_tf32(b.w));
        *(float4*)(sA + sw) = ac;
        *(float4*)(sB + sw) = bc;
    }
}
#endif

__global__ __launch_bounds__(256)
void gemm_tn(const float* __restrict__ A, const float* __restrict__ Bt,
             float* __restrict__ C)
{
    extern __shared__ char smem[];
    const int tid = threadIdx.x;
    const long bm = (long)blockIdx.y * 128;
    const long bn = (long)blockIdx.x * 128;

#if USE_TC
    const uint32_t smem_base = smem_u32(smem);
    const int wid = tid >> 5;
    const int lid = tid & 31;
    const uint32_t mb0 = smem_base + 8;
    const uint32_t mb1 = smem_base + 16;

    if (wid == 0) { TC_ALLOC(smem_base, 128); TC_RELINQ(); }
    if (tid == 0) { MBAR_INIT(mb0, 1); MBAR_INIT(mb1, 1); }
    __syncthreads();
    uint32_t tmem;
    asm volatile("ld.shared.b32 %0, [%1];" : "=r"(tmem) : "r"(smem_base));

    load_tile(smem, 0, A, Bt, bm, bn, 0, tid);
    uint32_t ph[2] = {0, 0};

    for (int c = 0; c < NCHUNK; c++) {
        const int s = c & 1;
        __syncthreads();
        if (wid == 0 && elect_one()) {
            FENCE_ASYNC_SHARED();
            uint64_t ad = make_desc(smem_base + SM_A(s));
            uint64_t bd = make_desc(smem_base + SM_B(s));
            #pragma unroll
            for (int k = 0; k < 4; k++)
                mma_tf32_ss(tmem, ad + k * 2, bd + k * 2, IDESC_TF32,
                            (c > 0) | (k > 0));
            TC_COMMIT(s ? mb1 : mb0);
        }
        if (c + 1 < NCHUNK) {
            const int ns = (c + 1) & 1;
            if (c >= 1) { MBAR_WAIT(ns ? mb1 : mb0, ph[ns]); ph[ns] ^= 1; }
            load_tile(smem, ns, A, Bt, bm, bn, (c + 1) * KCHUNK, tid);
        }
    }
    {
        const int ls = (NCHUNK - 1) & 1;
        MBAR_WAIT(ls ? mb1 : mb0, ph[ls]); ph[ls] ^= 1;
    }
    TC_FENCE_AFTER();

    if (wid < 4) {
        const long row = bm + wid * 32 + lid;
        float* crow = &C[row * (long)GK + bn];
        #pragma unroll
        for (int nb = 0; nb < 4; nb++) {
            uint32_t r[32];
            TC_LD_X32(r, tmem + nb * 32);
            TC_WAIT_LD();
            #pragma unroll
            for (int j = 0; j < 8; j++) {
                float4 v = make_float4(__uint_as_float(r[j*4+0]), __uint_as_float(r[j*4+1]),
                                       __uint_as_float(r[j*4+2]), __uint_as_float(r[j*4+3]));
                *(float4*)&crow[nb * 32 + j * 4] = v;
            }
        }
        TC_FENCE_BEFORE();
    }
    __syncthreads();
    if (tid == 0) { MBAR_INVAL(mb0); MBAR_INVAL(mb1); }
    if (wid == 0) TC_DEALLOC(tmem, 128);

#else  // SIMT fallback
    float* As = (float*)smem;
    float* Bs = (float*)smem + 16 * 128;
    const int tx = tid & 15, ty = tid >> 4;
    const int ar = tid >> 2, ak = (tid & 3) * 4;
    float acc[8][8];
    #pragma unroll
    for (int i = 0; i < 8; i++)
        #pragma unroll
        for (int j = 0; j < 8; j++) acc[i][j] = 0.f;
    for (int k0 = 0; k0 < GK; k0 += 16) {
        float4 a0 = *(const float4*)&A [(bm + ar)      * (long)GK + k0 + ak];
        float4 a1 = *(const float4*)&A [(bm + ar + 64) * (long)GK + k0 + ak];
        float4 b0 = *(const float4*)&Bt[(bn + ar)      * (long)GK + k0 + ak];
        float4 b1 = *(const float4*)&Bt[(bn + ar + 64) * (long)GK + k0 + ak];
        As[(ak+0)*128+ar]=a0.x; As[(ak+1)*128+ar]=a0.y; As[(ak+2)*128+ar]=a0.z; As[(ak+3)*128+ar]=a0.w;
        As[(ak+0)*128+ar+64]=a1.x; As[(ak+1)*128+ar+64]=a1.y; As[(ak+2)*128+ar+64]=a1.z; As[(ak+3)*128+ar+64]=a1.w;
        Bs[(ak+0)*128+ar]=b0.x; Bs[(ak+1)*128+ar]=b0.y; Bs[(ak+2)*128+ar]=b0.z; Bs[(ak+3)*128+ar]=b0.w;
        Bs[(ak+0)*128+ar+64]=b1.x; Bs[(ak+1)*128+ar+64]=b1.y; Bs[(ak+2)*128+ar+64]=b1.z; Bs[(ak+3)*128+ar+64]=b1.w;
        __syncthreads();
        #pragma unroll
        for (int kk = 0; kk < 16; kk++) {
            float ra[8], rb[8];
            *(float4*)&ra[0] = *(const float4*)&As[kk*128+ty*8];
            *(float4*)&ra[4] = *(const float4*)&As[kk*128+ty*8+4];
            *(float4*)&rb[0] = *(const float4*)&Bs[kk*128+tx*8];
            *(float4*)&rb[4] = *(const float4*)&Bs[kk*128+tx*8+4];
            #pragma unroll
            for (int i = 0; i < 8; i++)
                #pragma unroll
                for (int j = 0; j < 8; j++)
                    acc[i][j] = fmaf(ra[i], rb[j], acc[i][j]);
        }
        __syncthreads();
    }
    #pragma unroll
    for (int i = 0; i < 8; i++) {
        long row = (bm + ty*8 + i) * (long)GK + bn + tx*8;
        *(float4*)&C[row]   = make_float4(acc[i][0],acc[i][1],acc[i][2],acc[i][3]);
        *(float4*)&C[row+4] = make_float4(acc[i][4],acc[i][5],acc[i][6],acc[i][7]);
    }
#endif
}

// ---------------------------------------------------------------------------
// Transpose + tf32-round weights
// ---------------------------------------------------------------------------
__global__ __launch_bounds__(256) void transpose_cvt(
    const float* __restrict__ W, float* __restrict__ Wt)
{
    __shared__ float t[32][33];
    const int tx = threadIdx.x, ty = threadIdx.y;
    const int n0 = blockIdx.x * 32, k0 = blockIdx.y * 32;
    #pragma unroll
    for (int i = 0; i < 4; i++)
        t[ty + 8*i][tx] = W[(long)(k0 + ty + 8*i) * DMOD + n0 + tx];
    __syncthreads();
    #pragma unroll
    for (int i = 0; i < 4; i++)
        Wt[(long)(n0 + ty + 8*i) * DMOD + k0 + tx] = cvt_tf32(t[tx][ty + 8*i]);
}

// ---------------------------------------------------------------------------
// tcgen05 flash attention (causal), tf32 MMAs + fp32 softmax/accum
// CTA = (q-tile 128, head, batch); 256 threads (8 warps, 2 warpgroups)
// ---------------------------------------------------------------------------
#define AT_SQ    4096
#define AT_SK    (AT_SQ + 32768)
#define AT_SV    (AT_SK + 32768)
#define AT_SP    (AT_SV + 32768)
#define AT_SMEM  (AT_SP + 65536)       // 167936 bytes

__global__ __launch_bounds__(256)
void flash_attn_tc(const float* __restrict__ Qg, const float* __restrict__ Kg,
                   const float* __restrict__ Vg, float* __restrict__ Og)
{
    extern __shared__ char smem[];
    const int tid = threadIdx.x;
    const int qx = blockIdx.x, h = blockIdx.y, b = blockIdx.z;

#if USE_TC
    const uint32_t smem_base = smem_u32(smem);
    const int wid = tid >> 5;
    const int lid = tid & 31;
    const int wg  = wid >> 2;              // warpgroup 0/1 -> col halves
    const int row = (wid & 3) * 32 + lid;  // S/D row (TMEM subpartition)
    const uint32_t mb = smem_base + 16;
    float* red_m = (float*)(smem + 256);   // [2][128]
    float* red_s = (float*)(smem + 1536);  // [2][128]

    if (wid == 0) { TC_ALLOC(smem_base, 256); TC_RELINQ(); }
    if (tid == 0) MBAR_INIT(mb, 1);
    __syncthreads();
    uint32_t tmem;
    asm volatile("ld.shared.b32 %0, [%1];" : "=r"(tmem) : "r"(smem_base));
    const uint32_t tmem_S = tmem;          // cols 0..127
    const uint32_t tmem_O = tmem + 128;    // cols 128..191

    const long rowbase = (long)(b * SEQ) * DMOD + h * 64;
    const int q0 = qx * 128;

    // Load Q tile [128 rows x 64 d] -> two 32-d sub-tiles, SW128, tf32
    {
        const int r  = tid >> 3;
        const int kk = (tid & 7) * 4;
        #pragma unroll
        for (int s = 0; s < 2; s++) {
            #pragma unroll
            for (int p = 0; p < 4; p++) {
                int rr = p * 32 + r;
                float4 a = *(const float4*)&Qg[rowbase + (long)(q0 + rr) * DMOD + s*32 + kk];
                uint32_t off = (uint32_t)(rr * 128 + kk * 4);
                uint32_t sw  = off ^ ((off >> 3) & 0x70);
                *(float4*)(smem + AT_SQ + s*16384 + sw) =
                    make_float4(cvt_tf32(a.x), cvt_tf32(a.y), cvt_tf32(a.z), cvt_tf32(a.w));
            }
        }
    }

    const int cbase = wg * 64;             // this wg's S column base
    const int row_g = q0 + row;
    float mrow = -1e30f, lrow = 0.f;
    float acc[32];
    #pragma unroll
    for (int j = 0; j < 32; j++) acc[j] = 0.f;
    uint32_t ph = 0;
    const float scaling = 0.125f;

    for (int kt = 0; kt <= qx; kt++) {
        __syncthreads();   // prior iteration's smem/TMEM consumers done
        const int k0 = kt * 128;

        // Load K tile (two 32-d sub-tiles) and V tile transposed (4 kv-chunks)
        {
            const int r  = tid >> 3;
            const int kk = (tid & 7) * 4;
            #pragma unroll
            for (int s = 0; s < 2; s++) {
                #pragma unroll
                for (int p = 0; p < 4; p++) {
                    int rr = p * 32 + r;
                    float4 a = *(const float4*)&Kg[rowbase + (long)(k0 + rr) * DMOD + s*32 + kk];
                    uint32_t off = (uint32_t)(rr * 128 + kk * 4);
                    uint32_t sw  = off ^ ((off >> 3) & 0x70);
                    *(float4*)(smem + AT_SK + s*16384 + sw) =
                        make_float4(cvt_tf32(a.x), cvt_tf32(a.y), cvt_tf32(a.z), cvt_tf32(a.w));
                }
            }
            const int dv4 = (tid & 15) * 4;
            const int kv0 = tid >> 4;
            #pragma unroll
            for (int it = 0; it < 8; it++) {
                int kv = kv0 + it * 16;
                float4 v = *(const float4*)&Vg[rowbase + (long)(k0 + kv) * DMOD + dv4];
                char* basep = smem + AT_SV + (kv >> 5) * 8192;
                int within = kv & 31;
                float vv[4] = {v.x, v.y, v.z, v.w};
                #pragma unroll
                for (int j = 0; j < 4; j++) {
                    uint32_t off = (uint32_t)((dv4 + j) * 128 + within * 4);
                    uint32_t sw  = off ^ ((off >> 3) & 0x70);
                    *(float*)(basep + sw) = cvt_tf32(vv[j]);
                }
            }
        }
        __syncthreads();

        // S = Q @ K^T  (M=128, N=128, K=64 -> 8 MMAs)
        if (wid == 0 && elect_one()) {
            FENCE_ASYNC_SHARED();
            TC_FENCE_AFTER();
            #pragma unroll
            for (int s = 0; s < 2; s++) {
                uint64_t qd = make_desc(smem_base + AT_SQ + s*16384);
                uint64_t kd = make_desc(smem_base + AT_SK + s*16384);
                #pragma unroll
                for (int k = 0; k < 4; k++)
                    mma_tf32_ss(tmem_S, qd + k*2, kd + k*2, IDESC_N128, (s|k) != 0);
            }
            TC_COMMIT(mb);
        }
        MBAR_WAIT(mb, ph); ph ^= 1;
        TC_FENCE_AFTER();

        // Read this wg's 64 S columns
        uint32_t u0[32], u1[32];
        TC_LD_X32(u0, tmem_S + cbase);
        TC_LD_X32(u1, tmem_S + cbase + 32);
        TC_WAIT_LD();
        TC_FENCE_BEFORE();

        float sv[64];
        #pragma unroll
        for (int j = 0; j < 32; j++) {
            sv[j]      = __uint_as_float(u0[j]) * scaling;
            sv[32 + j] = __uint_as_float(u1[j]) * scaling;
        }
        if (kt == qx) {   // diagonal tile: mask col > row
            #pragma unroll
            for (int j = 0; j < 64; j++)
                if (k0 + cbase + j > row_g) sv[j] = -1e30f;
        }

        float lm = sv[0];
        #pragma unroll
        for (int j = 1; j < 64; j++) lm = fmaxf(lm, sv[j]);
        red_m[wg * 128 + row] = lm;
        __syncthreads();
        float mtile = fmaxf(red_m[row], red_m[128 + row]);
        float mnew  = fmaxf(mrow, mtile);
        float alpha = __expf(mrow - mnew);

        float ls = 0.f;
        #pragma unroll
        for (int j = 0; j < 64; j++) {
            float p = __expf(sv[j] - mnew);
            sv[j] = p;
            ls += p;
        }
        red_s[wg * 128 + row] = ls;

        // Write P (tf32) to smem: col c -> chunk c>>5, within c&31
        #pragma unroll
        for (int g = 0; g < 16; g++) {
            int c = cbase + g * 4;
            char* basep = smem + AT_SP + (c >> 5) * 16384;
            uint32_t off = (uint32_t)(row * 128 + (c & 31) * 4);
            uint32_t sw  = off ^ ((off >> 3) & 0x70);
            *(float4*)(basep + sw) = make_float4(
                cvt_tf32(sv[g*4+0]), cvt_tf32(sv[g*4+1]),
                cvt_tf32(sv[g*4+2]), cvt_tf32(sv[g*4+3]));
        }
        __syncthreads();   // P + red_s visible
        float ltile = red_s[row] + red_s[128 + row];
        lrow = lrow * alpha + ltile;
        mrow = mnew;

        // O_tile = P @ V^T  (M=128, N=64, K=128 -> 16 MMAs), no accumulate
        if (wid == 0 && elect_one()) {
            FENCE_ASYNC_SHARED();
            TC_FENCE_AFTER();
            #pragma unroll
            for (int c = 0; c < 4; c++) {
                uint64_t pd = make_desc(smem_base + AT_SP + c*16384);
                uint64_t vd = make_desc(smem_base + AT_SV + c*8192);
                #pragma unroll
                for (int k = 0; k < 4; k++)
                    mma_tf32_ss(tmem_O, pd + k*2, vd + k*2, IDESC_N64, (c|k) != 0);
            }
            TC_COMMIT(mb);
        }
        MBAR_WAIT(mb, ph); ph ^= 1;
        TC_FENCE_AFTER();

        uint32_t du[32];
        TC_LD_X32(du, tmem_O + wg * 32);
        TC_WAIT_LD();
        TC_FENCE_BEFORE();
        #pragma unroll
        for (int j = 0; j < 32; j++)
            acc[j] = acc[j] * alpha + __uint_as_float(du[j]);
    }

    // Write output: row, cols wg*32 .. +31
    {
        float inv = 1.f / lrow;
        float* orow = &Og[rowbase + (long)(q0 + row) * DMOD + wg * 32];
        #pragma unroll
        for (int g = 0; g < 8; g++) {
            *(float4*)&orow[g * 4] = make_float4(
                acc[g*4+0]*inv, acc[g*4+1]*inv, acc[g*4+2]*inv, acc[g*4+3]*inv);
        }
    }
    __syncthreads();
    if (tid == 0) MBAR_INVAL(mb);
    if (wid == 0) TC_DEALLOC(tmem, 256);

#else  // ------- trivial fallback (never selected on sm_103a) -------
    if (tid < 128) {
        const long rowbase = (long)(b * SEQ) * DMOD + h * 64;
        const int q = qx * 128 + tid;
        float qreg[64];
        #pragma unroll
        for (int d = 0; d < 64; d++) qreg[d] = Qg[rowbase + (long)q * DMOD + d];
        float m = -1e30f, l = 0.f, acc[64];
        #pragma unroll
        for (int d = 0; d < 64; d++) acc[d] = 0.f;
        for (int kv = 0; kv <= q; kv++) {
            const float* kr = &Kg[rowbase + (long)kv * DMOD];
            float s = 0.f;
            for (int d = 0; d < 64; d++) s += qreg[d] * kr[d];
            s *= 0.125f;
            float mn = fmaxf(m, s);
            float al = __expf(m - mn), p = __expf(s - mn);
            l = l * al + p;
            const float* vr = &Vg[rowbase + (long)kv * DMOD];
            for (int d = 0; d < 64; d++) acc[d] = acc[d] * al + p * vr[d];
            m = mn;
        }
        float inv = 1.f / l;
        for (int d = 0; d < 64; d++)
            Og[rowbase + (long)q * DMOD + d] = acc[d] * inv;
    }
#endif
}

// ---------------------------------------------------------------------------
// Host launcher
// ---------------------------------------------------------------------------
extern "C" void kernel_launch(void* const* d_in, const int* in_sizes, int n_in,
                              void* d_out, int out_size)
{
    const float* queries = (const float*)d_in[0];
    const float* keys    = (const float*)d_in[1];
    const float* values  = (const float*)d_in[2];
    // d_in[3] = mask — causal, analytic
    const float* W_Q = (const float*)d_in[4];
    const float* W_K = (const float*)d_in[5];
    const float* W_V = (const float*)d_in[6];
    const float* W_O = (const float*)d_in[7];
    float* out = (float*)d_out;

    float *Qb, *Kb, *Vb, *Ab, *Wt;
    cudaGetSymbolAddress((void**)&Qb, g_Q);
    cudaGetSymbolAddress((void**)&Kb, g_K);
    cudaGetSymbolAddress((void**)&Vb, g_V);
    cudaGetSymbolAddress((void**)&Ab, g_A);
    cudaGetSymbolAddress((void**)&Wt, g_Wt);

    cudaFuncSetAttribute(gemm_tn, cudaFuncAttributeMaxDynamicSharedMemorySize,
                         GEMM_SMEM);
    cudaFuncSetAttribute(flash_attn_tc, cudaFuncAttributeMaxDynamicSharedMemorySize,
                         AT_SMEM);

    dim3 tgrid(32, 32), tblk(32, 8);
    dim3 ggrid(DMOD / 128, MROWS / 128);

    transpose_cvt<<<tgrid, tblk>>>(W_Q, Wt);
    gemm_tn<<<ggrid, 256, GEMM_SMEM>>>(queries, Wt, Qb);

    transpose_cvt<<<tgrid, tblk>>>(W_K, Wt);
    gemm_tn<<<ggrid, 256, GEMM_SMEM>>>(keys, Wt, Kb);

    transpose_cvt<<<tgrid, tblk>>>(W_V, Wt);
    gemm_tn<<<ggrid, 256, GEMM_SMEM>>>(values, Wt, Vb);

    dim3 agrid(SEQ / 128, NHEAD, BATCH);   // (16, 16, 4)
    flash_attn_tc<<<agrid, 256, AT_SMEM>>>(Qb, Kb, Vb, Ab);

    transpose_cvt<<<tgrid, tblk>>>(W_O, Wt);
    gemm_tn<<<ggrid, 256, GEMM_SMEM>>>(Ab, Wt, out);
}

// round 5
// speedup vs baseline: 9.2801x; 1.3440x over previous
#include <cuda_runtime.h>
#include <cuda.h>
#include <math.h>
#include <stdint.h>

// Problem dims (fixed)
#define BATCH 4
#define SEQ   2048
#define DMOD  1024
#define NHEAD 16
#define HDIM  64
#define MROWS (BATCH*SEQ)   // 8192

// Scratch (device globals; no allocation allowed)
__device__ float g_Q[BATCH*SEQ*DMOD];
__device__ float g_K[BATCH*SEQ*DMOD];
__device__ float g_V[BATCH*SEQ*DMOD];
__device__ float g_A[BATCH*SEQ*DMOD];
__device__ float g_X[BATCH*SEQ*DMOD];   // tf32-rounded activation staging
__device__ float g_Wt[DMOD*DMOD];       // transposed + tf32-rounded weight

// tcgen05 only exists in the arch-SPECIFIC (sm_103a) compilation pass.
#if defined(__CUDA_ARCH_FEAT_SM103_ALL) || \
    (defined(__CUDA_ARCH_SPECIFIC__) && (__CUDA_ARCH_SPECIFIC__ == 1030)) || \
    defined(__CUDA_ARCH_FEAT_SM100_ALL)
#define USE_TC 1
#else
#define USE_TC 0
#endif

// ---------------------------------------------------------------------------
// Helpers
// ---------------------------------------------------------------------------
__device__ __forceinline__ float cvt_tf32(float x) {
    uint32_t u;
    asm("cvt.rna.tf32.f32 %0, %1;" : "=r"(u) : "f"(x));
    return __uint_as_float(u);
}

#if USE_TC
__device__ __forceinline__ uint32_t smem_u32(const void* p) {
    uint32_t a;
    asm("{ .reg .u64 t; cvta.to.shared.u64 t, %1; cvt.u32.u64 %0, t; }"
        : "=r"(a) : "l"(p));
    return a;
}
__device__ __forceinline__ uint32_t elect_one() {
    uint32_t pred;
    asm volatile("{\n\t.reg .pred p;\n\telect.sync _|p, 0xFFFFFFFF;\n\t"
                 "selp.b32 %0, 1, 0, p;\n\t}" : "=r"(pred));
    return pred;
}

#define CP_ASYNC16(dst, src) \
    asm volatile("cp.async.cg.shared.global [%0], [%1], 16;" \
        :: "r"(dst), "l"(src) : "memory")
#define CP_COMMIT() asm volatile("cp.async.commit_group;" ::: "memory")
#define CP_WAIT0()  asm volatile("cp.async.wait_group 0;" ::: "memory")
#define CP_WAIT1()  asm volatile("cp.async.wait_group 1;" ::: "memory")

#define MBAR_INIT(a, n) \
    asm volatile("mbarrier.init.shared.b64 [%0], %1;" :: "r"(a), "r"(n) : "memory")
#define MBAR_INVAL(a) \
    asm volatile("mbarrier.inval.shared.b64 [%0];" :: "r"(a) : "memory")
#define MBAR_WAIT(a, ph) do {                                                  \
    uint32_t _m = (a), _p = (ph), _d;                                          \
    asm volatile("{\n\t.reg .pred p;\n\t"                                      \
        "mbarrier.try_wait.parity.acquire.cta.shared::cta.b64 p, [%1], %2;\n\t"\
        "selp.b32 %0, 1, 0, p;\n\t}" : "=r"(_d) : "r"(_m), "r"(_p) : "memory");\
    if (!_d) {                                                                 \
        asm volatile("{\n\t.reg .pred P1;\n\tWL_%=:\n\t"                       \
            "mbarrier.try_wait.parity.acquire.cta.shared::cta.b64 P1, [%0], %1, 0x989680;\n\t" \
            "@P1 bra.uni WD_%=;\n\tbra.uni WL_%=;\n\tWD_%=:\n\t}"              \
            :: "r"(_m), "r"(_p) : "memory");                                   \
    }                                                                          \
} while (0)

#define TC_ALLOC(smem_addr, n) \
    asm volatile("tcgen05.alloc.cta_group::1.sync.aligned.shared::cta.b32 [%0], %1;" \
        :: "r"(smem_addr), "r"((uint32_t)(n)) : "memory")
#define TC_DEALLOC(tmem, n) \
    asm volatile("tcgen05.dealloc.cta_group::1.sync.aligned.b32 %0, %1;" \
        :: "r"(tmem), "r"((uint32_t)(n)))
#define TC_RELINQ() \
    asm volatile("tcgen05.relinquish_alloc_permit.cta_group::1.sync.aligned;")
#define TC_COMMIT(mbar) \
    asm volatile("tcgen05.commit.cta_group::1.mbarrier::arrive::one.shared::cluster.b64 [%0];" \
        :: "r"(mbar) : "memory")
#define TC_FENCE_AFTER()  asm volatile("tcgen05.fence::after_thread_sync;" ::: "memory")
#define TC_FENCE_BEFORE() asm volatile("tcgen05.fence::before_thread_sync;" ::: "memory")
#define FENCE_ASYNC_SHARED() asm volatile("fence.proxy.async.shared::cta;" ::: "memory")
#define TC_WAIT_LD() asm volatile("tcgen05.wait::ld.sync.aligned;" ::: "memory")

#define TC_LD_X32(r, tmem) \
    asm volatile("tcgen05.ld.sync.aligned.32x32b.x32.b32 " \
        "{%0,%1,%2,%3,%4,%5,%6,%7,%8,%9,%10,%11,%12,%13,%14,%15," \
        "%16,%17,%18,%19,%20,%21,%22,%23,%24,%25,%26,%27,%28,%29,%30,%31}, [%32];" \
        : "=r"((r)[0]),"=r"((r)[1]),"=r"((r)[2]),"=r"((r)[3]), \
          "=r"((r)[4]),"=r"((r)[5]),"=r"((r)[6]),"=r"((r)[7]), \
          "=r"((r)[8]),"=r"((r)[9]),"=r"((r)[10]),"=r"((r)[11]), \
          "=r"((r)[12]),"=r"((r)[13]),"=r"((r)[14]),"=r"((r)[15]), \
          "=r"((r)[16]),"=r"((r)[17]),"=r"((r)[18]),"=r"((r)[19]), \
          "=r"((r)[20]),"=r"((r)[21]),"=r"((r)[22]),"=r"((r)[23]), \
          "=r"((r)[24]),"=r"((r)[25]),"=r"((r)[26]),"=r"((r)[27]), \
          "=r"((r)[28]),"=r"((r)[29]),"=r"((r)[30]),"=r"((r)[31]) \
        : "r"(tmem))

// SMEM descriptor: SW128, Blackwell, LBO=1, SBO=64 (K-major)
static __device__ __forceinline__ uint64_t make_desc(uint32_t addr) {
    const uint64_t base =
        (uint64_t(2) << 61) | (uint64_t(1) << 46) | (uint64_t(64) << 32) | (uint64_t(1) << 16);
    return base | ((uint64_t)(addr >> 4) & 0x3FFF);
}

__device__ __forceinline__ void mma_tf32_ss(
    uint32_t d, uint64_t ad, uint64_t bd, uint32_t idesc, uint32_t en)
{
    asm volatile("{\n\t.reg .pred p;\n\tsetp.ne.u32 p, %5, 0;\n\t"
        "tcgen05.mma.cta_group::1.kind::tf32 [%0], %1, %2, %3, {%4,%4,%4,%4}, p;\n\t}"
        :: "r"(d), "l"(ad), "l"(bd), "r"(idesc), "r"(0u), "r"(en) : "memory");
}
#define IDESC_N128 0x8200910u
#define IDESC_N64  0x8100910u
#endif  // USE_TC

// ---------------------------------------------------------------------------
// Elementwise tf32 rounding pass (activations)
// ---------------------------------------------------------------------------
__global__ __launch_bounds__(256) void cvt_tensor(
    const float* __restrict__ in, float* __restrict__ out)
{
    long i = ((long)blockIdx.x * 256 + threadIdx.x) * 4;
    const long n = (long)MROWS * DMOD;
    for (; i < n; i += (long)gridDim.x * 256 * 4) {
        float4 v = *(const float4*)&in[i];
        *(float4*)&out[i] = make_float4(cvt_tf32(v.x), cvt_tf32(v.y),
                                        cvt_tf32(v.z), cvt_tf32(v.w));
    }
}

// ---------------------------------------------------------------------------
// GEMM: C[M,1024] = A[M,1024] @ Bt^T ; A,Bt pre-rounded tf32 (stored fp32)
// cp.async 3-stage pipeline, 128x128 tile, K-chunk 32.
// ---------------------------------------------------------------------------
#define GK        1024
#define KCHUNK    32
#define NCHUNK    (GK / KCHUNK)
#define STAGE_B   32768
#define SM_HDR    1024
#define SM_A(s)   (SM_HDR + (s) * STAGE_B)
#define SM_B(s)   (SM_HDR + (s) * STAGE_B + 16384)
#define GEMM_SMEM (SM_HDR + 3 * STAGE_B)   // 99328

#if USE_TC
__device__ __forceinline__ void load_tile_cp(
    uint32_t smem_base, int stage, const float* __restrict__ A,
    const float* __restrict__ Bt, long bm, long bn, int k0, int tid)
{
    const int r  = tid >> 3;
    const int kk = (tid & 7) * 4;
    const uint32_t sA = smem_base + SM_A(stage);
    const uint32_t sB = smem_base + SM_B(stage);
    #pragma unroll
    for (int p = 0; p < 4; p++) {
        int row = p * 32 + r;
        uint32_t off = (uint32_t)(row * 128 + kk * 4);
        uint32_t sw  = off ^ ((off >> 3) & 0x70);
        CP_ASYNC16(sA + sw, &A [(bm + row) * (long)GK + k0 + kk]);
        CP_ASYNC16(sB + sw, &Bt[(bn + row) * (long)GK + k0 + kk]);
    }
}
#endif

__global__ __launch_bounds__(256)
void gemm_tn(const float* __restrict__ A, const float* __restrict__ Bt,
             float* __restrict__ C, int round_out)
{
    extern __shared__ char smem[];
    const int tid = threadIdx.x;
    const long bm = (long)blockIdx.y * 128;
    const long bn = (long)blockIdx.x * 128;

#if USE_TC
    const uint32_t smem_base = smem_u32(smem);
    const int wid = tid >> 5;
    const int lid = tid & 31;
    const uint32_t mb[3] = {smem_base + 8, smem_base + 16, smem_base + 24};

    if (wid == 0) { TC_ALLOC(smem_base, 128); TC_RELINQ(); }
    if (tid == 0) { MBAR_INIT(mb[0], 1); MBAR_INIT(mb[1], 1); MBAR_INIT(mb[2], 1); }
    __syncthreads();
    uint32_t tmem;
    asm volatile("ld.shared.b32 %0, [%1];" : "=r"(tmem) : "r"(smem_base));

    load_tile_cp(smem_base, 0, A, Bt, bm, bn, 0, tid);       CP_COMMIT();
    load_tile_cp(smem_base, 1, A, Bt, bm, bn, KCHUNK, tid);  CP_COMMIT();
    uint32_t ph[3] = {0, 0, 0};

    for (int c = 0; c < NCHUNK; c++) {
        const int s = c % 3;
        if (c < NCHUNK - 1) { CP_WAIT1(); } else { CP_WAIT0(); }
        __syncthreads();

        if (wid == 0 && elect_one()) {
            FENCE_ASYNC_SHARED();
            uint64_t ad = make_desc(smem_base + SM_A(s));
            uint64_t bd = make_desc(smem_base + SM_B(s));
            #pragma unroll
            for (int k = 0; k < 4; k++)
                mma_tf32_ss(tmem, ad + k * 2, bd + k * 2, IDESC_N128,
                            (c > 0) | (k > 0));
            TC_COMMIT(mb[s]);
        }

        if (c + 2 < NCHUNK) {
            const int fs = (c + 2) % 3;
            if (c >= 1) { MBAR_WAIT(mb[fs], ph[fs]); ph[fs] ^= 1; }
            load_tile_cp(smem_base, fs, A, Bt, bm, bn, (c + 2) * KCHUNK, tid);
            CP_COMMIT();
        }
    }
    {
        const int ls = (NCHUNK - 1) % 3;
        MBAR_WAIT(mb[ls], ph[ls]); ph[ls] ^= 1;
    }
    TC_FENCE_AFTER();

    if (wid < 4) {
        const long row = bm + wid * 32 + lid;
        float* crow = &C[row * (long)GK + bn];
        #pragma unroll
        for (int nb = 0; nb < 4; nb++) {
            uint32_t r[32];
            TC_LD_X32(r, tmem + nb * 32);
            TC_WAIT_LD();
            if (round_out) {
                #pragma unroll
                for (int j = 0; j < 8; j++)
                    *(float4*)&crow[nb * 32 + j * 4] = make_float4(
                        cvt_tf32(__uint_as_float(r[j*4+0])), cvt_tf32(__uint_as_float(r[j*4+1])),
                        cvt_tf32(__uint_as_float(r[j*4+2])), cvt_tf32(__uint_as_float(r[j*4+3])));
            } else {
                #pragma unroll
                for (int j = 0; j < 8; j++)
                    *(float4*)&crow[nb * 32 + j * 4] = make_float4(
                        __uint_as_float(r[j*4+0]), __uint_as_float(r[j*4+1]),
                        __uint_as_float(r[j*4+2]), __uint_as_float(r[j*4+3]));
            }
        }
        TC_FENCE_BEFORE();
    }
    __syncthreads();
    if (tid == 0) { MBAR_INVAL(mb[0]); MBAR_INVAL(mb[1]); MBAR_INVAL(mb[2]); }
    if (wid == 0) TC_DEALLOC(tmem, 128);

#else  // SIMT fallback
    float* As = (float*)smem;
    float* Bs = (float*)smem + 16 * 128;
    const int tx = tid & 15, ty = tid >> 4;
    const int ar = tid >> 2, ak = (tid & 3) * 4;
    float acc[8][8];
    #pragma unroll
    for (int i = 0; i < 8; i++)
        #pragma unroll
        for (int j = 0; j < 8; j++) acc[i][j] = 0.f;
    for (int k0 = 0; k0 < GK; k0 += 16) {
        float4 a0 = *(const float4*)&A [(bm + ar)      * (long)GK + k0 + ak];
        float4 a1 = *(const float4*)&A [(bm + ar + 64) * (long)GK + k0 + ak];
        float4 b0 = *(const float4*)&Bt[(bn + ar)      * (long)GK + k0 + ak];
        float4 b1 = *(const float4*)&Bt[(bn + ar + 64) * (long)GK + k0 + ak];
        As[(ak+0)*128+ar]=a0.x; As[(ak+1)*128+ar]=a0.y; As[(ak+2)*128+ar]=a0.z; As[(ak+3)*128+ar]=a0.w;
        As[(ak+0)*128+ar+64]=a1.x; As[(ak+1)*128+ar+64]=a1.y; As[(ak+2)*128+ar+64]=a1.z; As[(ak+3)*128+ar+64]=a1.w;
        Bs[(ak+0)*128+ar]=b0.x; Bs[(ak+1)*128+ar]=b0.y; Bs[(ak+2)*128+ar]=b0.z; Bs[(ak+3)*128+ar]=b0.w;
        Bs[(ak+0)*128+ar+64]=b1.x; Bs[(ak+1)*128+ar+64]=b1.y; Bs[(ak+2)*128+ar+64]=b1.z; Bs[(ak+3)*128+ar+64]=b1.w;
        __syncthreads();
        #pragma unroll
        for (int kk = 0; kk < 16; kk++) {
            float ra[8], rb[8];
            *(float4*)&ra[0] = *(const float4*)&As[kk*128+ty*8];
            *(float4*)&ra[4] = *(const float4*)&As[kk*128+ty*8+4];
            *(float4*)&rb[0] = *(const float4*)&Bs[kk*128+tx*8];
            *(float4*)&rb[4] = *(const float4*)&Bs[kk*128+tx*8+4];
            #pragma unroll
            for (int i = 0; i < 8; i++)
                #pragma unroll
                for (int j = 0; j < 8; j++)
                    acc[i][j] = fmaf(ra[i], rb[j], acc[i][j]);
        }
        __syncthreads();
    }
    #pragma unroll
    for (int i = 0; i < 8; i++) {
        long row = (bm + ty*8 + i) * (long)GK + bn + tx*8;
        *(float4*)&C[row]   = make_float4(acc[i][0],acc[i][1],acc[i][2],acc[i][3]);
        *(float4*)&C[row+4] = make_float4(acc[i][4],acc[i][5],acc[i][6],acc[i][7]);
    }
#endif
}

// ---------------------------------------------------------------------------
// Transpose + tf32-round weights
// ---------------------------------------------------------------------------
__global__ __launch_bounds__(256) void transpose_cvt(
    const float* __restrict__ W, float* __restrict__ Wt)
{
    __shared__ float t[32][33];
    const int tx = threadIdx.x, ty = threadIdx.y;
    const int n0 = blockIdx.x * 32, k0 = blockIdx.y * 32;
    #pragma unroll
    for (int i = 0; i < 4; i++)
        t[ty + 8*i][tx] = W[(long)(k0 + ty + 8*i) * DMOD + n0 + tx];
    __syncthreads();
    #pragma unroll
    for (int i = 0; i < 4; i++)
        Wt[(long)(n0 + ty + 8*i) * DMOD + k0 + tx] = cvt_tf32(t[tx][ty + 8*i]);
}

// ---------------------------------------------------------------------------
// tcgen05 flash attention (causal). K double-buffered (cp.async prefetch),
// deferred PV fold, P in smem (SS mode). Inputs pre-rounded tf32.
// ---------------------------------------------------------------------------
#define AT_SQ    3072
#define AT_SK    (AT_SQ + 32768)           // 2 x 32KB
#define AT_SV    (AT_SK + 65536)           // 32KB (4 x 8KB chunks)
#define AT_SP    (AT_SV + 32768)           // 64KB (4 x 16KB chunks)
#define AT_SMEM  (AT_SP + 65536)           // 199680

__global__ __launch_bounds__(256)
void flash_attn_tc(const float* __restrict__ Qg, const float* __restrict__ Kg,
                   const float* __restrict__ Vg, float* __restrict__ Og)
{
    extern __shared__ char smem[];
    const int tid = threadIdx.x;
    const int qx = blockIdx.x, h = blockIdx.y, b = blockIdx.z;

#if USE_TC
    const uint32_t smem_base = smem_u32(smem);
    const int wid = tid >> 5;
    const int lid = tid & 31;
    const int wg  = wid >> 2;
    const int row = (wid & 3) * 32 + lid;
    const uint32_t mb_s = smem_base + 16;
    const uint32_t mb_o = smem_base + 32;
    float* red_m = (float*)(smem + 1024);   // [2][128]
    float* red_s = (float*)(smem + 2048);   // [2][128]

    if (wid == 0) { TC_ALLOC(smem_base, 256); TC_RELINQ(); }
    if (tid == 0) { MBAR_INIT(mb_s, 1); MBAR_INIT(mb_o, 1); }
    __syncthreads();
    uint32_t tmem;
    asm volatile("ld.shared.b32 %0, [%1];" : "=r"(tmem) : "r"(smem_base));
    const uint32_t tmem_S = tmem;
    const uint32_t tmem_O = tmem + 128;

    const long rowbase = (long)(b * SEQ) * DMOD + h * 64;
    const int q0 = qx * 128;
    const int r8  = tid >> 3;
    const int kk8 = (tid & 7) * 4;

    // Q tile via cp.async (pre-rounded tf32)
    #pragma unroll
    for (int s = 0; s < 2; s++)
        #pragma unroll
        for (int p = 0; p < 4; p++) {
            int rr = p * 32 + r8;
            uint32_t off = (uint32_t)(rr * 128 + kk8 * 4);
            uint32_t sw  = off ^ ((off >> 3) & 0x70);
            CP_ASYNC16(smem_base + AT_SQ + s*16384 + sw,
                       &Qg[rowbase + (long)(q0 + rr) * DMOD + s*32 + kk8]);
        }
    CP_COMMIT();
    // K(0) via cp.async into buffer 0
    #pragma unroll
    for (int s = 0; s < 2; s++)
        #pragma unroll
        for (int p = 0; p < 4; p++) {
            int rr = p * 32 + r8;
            uint32_t off = (uint32_t)(rr * 128 + kk8 * 4);
            uint32_t sw  = off ^ ((off >> 3) & 0x70);
            CP_ASYNC16(smem_base + AT_SK + s*16384 + sw,
                       &Kg[rowbase + (long)rr * DMOD + s*32 + kk8]);
        }
    CP_COMMIT();

    const int cbase = wg * 64;
    const int row_g = q0 + row;
    float mrow = -1e30f, lrow = 0.f, alpha_prev = 1.f;
    float acc[32];
    #pragma unroll
    for (int j = 0; j < 32; j++) acc[j] = 0.f;
    uint32_t ph_s = 0, ph_o = 0;
    const float scaling = 0.125f;

    CP_WAIT0();
    __syncthreads();   // Q + K(0) resident

    for (int kt = 0; kt <= qx; kt++) {
        const int kb = kt & 1;
        const int k0 = kt * 128;

        // Issue S(kt) = Q @ K(kt)^T
        if (wid == 0 && elect_one()) {
            FENCE_ASYNC_SHARED();
            TC_FENCE_AFTER();
            #pragma unroll
            for (int s = 0; s < 2; s++) {
                uint64_t qd = make_desc(smem_base + AT_SQ + s*16384);
                uint64_t kd = make_desc(smem_base + AT_SK + kb*32768 + s*16384);
                #pragma unroll
                for (int k = 0; k < 4; k++)
                    mma_tf32_ss(tmem_S, qd + k*2, kd + k*2, IDESC_N128, (s|k) != 0);
            }
            TC_COMMIT(mb_s);
        }

        // Prefetch K(kt+1) into the other buffer
        if (kt < qx) {
            const int nk0 = k0 + 128;
            #pragma unroll
            for (int s = 0; s < 2; s++)
                #pragma unroll
                for (int p = 0; p < 4; p++) {
                    int rr = p * 32 + r8;
                    uint32_t off = (uint32_t)(rr * 128 + kk8 * 4);
                    uint32_t sw  = off ^ ((off >> 3) & 0x70);
                    CP_ASYNC16(smem_base + AT_SK + (kb^1)*32768 + s*16384 + sw,
                               &Kg[rowbase + (long)(nk0 + rr) * DMOD + s*32 + kk8]);
                }
            CP_COMMIT();
        }

        // Fold PV(kt-1)
        if (kt > 0) {
            MBAR_WAIT(mb_o, ph_o); ph_o ^= 1;
            TC_FENCE_AFTER();
            uint32_t du[32];
            TC_LD_X32(du, tmem_O + wg * 32);
            TC_WAIT_LD();
            TC_FENCE_BEFORE();
            #pragma unroll
            for (int j = 0; j < 32; j++)
                acc[j] = acc[j] * alpha_prev + __uint_as_float(du[j]);
        }

        // Load V(kt) (transposed into smem; buffer free after mb_o wait)
        {
            const int dv4 = (tid & 15) * 4;
            const int kv0 = tid >> 4;
            #pragma unroll
            for (int it = 0; it < 8; it++) {
                int kv = kv0 + it * 16;
                float4 v = *(const float4*)&Vg[rowbase + (long)(k0 + kv) * DMOD + dv4];
                char* basep = smem + AT_SV + (kv >> 5) * 8192;
                int within = kv & 31;
                float vv[4] = {v.x, v.y, v.z, v.w};
                #pragma unroll
                for (int j = 0; j < 4; j++) {
                    uint32_t off = (uint32_t)((dv4 + j) * 128 + within * 4);
                    uint32_t sw  = off ^ ((off >> 3) & 0x70);
                    *(float*)(basep + sw) = vv[j];
                }
            }
        }

        // Wait S, read this wg's 64 columns
        MBAR_WAIT(mb_s, ph_s); ph_s ^= 1;
        TC_FENCE_AFTER();
        uint32_t u0[32], u1[32];
        TC_LD_X32(u0, tmem_S + cbase);
        TC_LD_X32(u1, tmem_S + cbase + 32);
        TC_WAIT_LD();
        TC_FENCE_BEFORE();

        float sv[64];
        #pragma unroll
        for (int j = 0; j < 32; j++) {
            sv[j]      = __uint_as_float(u0[j]) * scaling;
            sv[32 + j] = __uint_as_float(u1[j]) * scaling;
        }
        if (kt == qx) {
            #pragma unroll
            for (int j = 0; j < 64; j++)
                if (k0 + cbase + j > row_g) sv[j] = -1e30f;
        }

        float lm = sv[0];
        #pragma unroll
        for (int j = 1; j < 64; j++) lm = fmaxf(lm, sv[j]);
        red_m[wg * 128 + row] = lm;
        __syncthreads();
        float mtile = fmaxf(red_m[row], red_m[128 + row]);
        float mnew  = fmaxf(mrow, mtile);
        float alpha = __expf(mrow - mnew);

        float ls = 0.f;
        #pragma unroll
        for (int j = 0; j < 64; j++) {
            float p = __expf(sv[j] - mnew);
            sv[j] = p;
            ls += p;
        }
        red_s[wg * 128 + row] = ls;

        // Write P (tf32) to smem
        #pragma unroll
        for (int g = 0; g < 16; g++) {
            int c = cbase + g * 4;
            char* basep = smem + AT_SP + (c >> 5) * 16384;
            uint32_t off = (uint32_t)(row * 128 + (c & 31) * 4);
            uint32_t sw  = off ^ ((off >> 3) & 0x70);
            *(float4*)(basep + sw) = make_float4(
                cvt_tf32(sv[g*4+0]), cvt_tf32(sv[g*4+1]),
                cvt_tf32(sv[g*4+2]), cvt_tf32(sv[g*4+3]));
        }

        CP_WAIT0();        // K(kt+1) arrived
        __syncthreads();   // P, V, red_s, K(kt+1) visible CTA-wide

        float ltile = red_s[row] + red_s[128 + row];
        lrow = lrow * alpha + ltile;
        mrow = mnew;
        alpha_prev = alpha;

        // Issue PV(kt) -> tmem_O (overwrite)
        if (wid == 0 && elect_one()) {
            FENCE_ASYNC_SHARED();
            TC_FENCE_AFTER();
            #pragma unroll
            for (int c = 0; c < 4; c++) {
                uint64_t pd = make_desc(smem_base + AT_SP + c*16384);
                uint64_t vd = make_desc(smem_base + AT_SV + c*8192);
                #pragma unroll
                for (int k = 0; k < 4; k++)
                    mma_tf32_ss(tmem_O, pd + k*2, vd + k*2, IDESC_N64, (c|k) != 0);
            }
            TC_COMMIT(mb_o);
        }
    }

    // Final fold + output (tf32-rounded for the W_O GEMM)
    MBAR_WAIT(mb_o, ph_o); ph_o ^= 1;
    TC_FENCE_AFTER();
    {
        uint32_t du[32];
        TC_LD_X32(du, tmem_O + wg * 32);
        TC_WAIT_LD();
        TC_FENCE_BEFORE();
        #pragma unroll
        for (int j = 0; j < 32; j++)
            acc[j] = acc[j] * alpha_prev + __uint_as_float(du[j]);

        float inv = 1.f / lrow;
        float* orow = &Og[rowbase + (long)(q0 + row) * DMOD + wg * 32];
        #pragma unroll
        for (int g = 0; g < 8; g++)
            *(float4*)&orow[g * 4] = make_float4(
                cvt_tf32(acc[g*4+0]*inv), cvt_tf32(acc[g*4+1]*inv),
                cvt_tf32(acc[g*4+2]*inv), cvt_tf32(acc[g*4+3]*inv));
    }
    __syncthreads();
    if (tid == 0) { MBAR_INVAL(mb_s); MBAR_INVAL(mb_o); }
    if (wid == 0) TC_DEALLOC(tmem, 256);

#else  // trivial fallback (never selected on sm_103a)
    if (tid < 128) {
        const long rowbase = (long)(b * SEQ) * DMOD + h * 64;
        const int q = qx * 128 + tid;
        float qreg[64];
        #pragma unroll
        for (int d = 0; d < 64; d++) qreg[d] = Qg[rowbase + (long)q * DMOD + d];
        float m = -1e30f, l = 0.f, acc[64];
        #pragma unroll
        for (int d = 0; d < 64; d++) acc[d] = 0.f;
        for (int kv = 0; kv <= q; kv++) {
            const float* kr = &Kg[rowbase + (long)kv * DMOD];
            float s = 0.f;
            for (int d = 0; d < 64; d++) s += qreg[d] * kr[d];
            s *= 0.125f;
            float mn = fmaxf(m, s);
            float al = __expf(m - mn), p = __expf(s - mn);
            l = l * al + p;
            const float* vr = &Vg[rowbase + (long)kv * DMOD];
            for (int d = 0; d < 64; d++) acc[d] = acc[d] * al + p * vr[d];
            m = mn;
        }
        float inv = 1.f / l;
        for (int d = 0; d < 64; d++)
            Og[rowbase + (long)q * DMOD + d] = acc[d] * inv;
    }
#endif
}

// ---------------------------------------------------------------------------
// Host launcher
// ---------------------------------------------------------------------------
extern "C" void kernel_launch(void* const* d_in, const int* in_sizes, int n_in,
                              void* d_out, int out_size)
{
    const float* queries = (const float*)d_in[0];
    const float* keys    = (const float*)d_in[1];
    const float* values  = (const float*)d_in[2];
    // d_in[3] = mask — causal, analytic
    const float* W_Q = (const float*)d_in[4];
    const float* W_K = (const float*)d_in[5];
    const float* W_V = (const float*)d_in[6];
    const float* W_O = (const float*)d_in[7];
    float* out = (float*)d_out;

    float *Qb, *Kb, *Vb, *Ab, *Xb, *Wt;
    cudaGetSymbolAddress((void**)&Qb, g_Q);
    cudaGetSymbolAddress((void**)&Kb, g_K);
    cudaGetSymbolAddress((void**)&Vb, g_V);
    cudaGetSymbolAddress((void**)&Ab, g_A);
    cudaGetSymbolAddress((void**)&Xb, g_X);
    cudaGetSymbolAddress((void**)&Wt, g_Wt);

    cudaFuncSetAttribute(gemm_tn, cudaFuncAttributeMaxDynamicSharedMemorySize,
                         GEMM_SMEM);
    cudaFuncSetAttribute(flash_attn_tc, cudaFuncAttributeMaxDynamicSharedMemorySize,
                         AT_SMEM);

    dim3 tgrid(32, 32), tblk(32, 8);
    dim3 ggrid(DMOD / 128, MROWS / 128);
    const int cvt_blocks = 2048;

    transpose_cvt<<<tgrid, tblk>>>(W_Q, Wt);
    cvt_tensor<<<cvt_blocks, 256>>>(queries, Xb);
    gemm_tn<<<ggrid, 256, GEMM_SMEM>>>(Xb, Wt, Qb, 1);

    transpose_cvt<<<tgrid, tblk>>>(W_K, Wt);
    cvt_tensor<<<cvt_blocks, 256>>>(keys, Xb);
    gemm_tn<<<ggrid, 256, GEMM_SMEM>>>(Xb, Wt, Kb, 1);

    transpose_cvt<<<tgrid, tblk>>>(W_V, Wt);
    cvt_tensor<<<cvt_blocks, 256>>>(values, Xb);
    gemm_tn<<<ggrid, 256, GEMM_SMEM>>>(Xb, Wt, Vb, 1);

    dim3 agrid(SEQ / 128, NHEAD, BATCH);
    flash_attn_tc<<<agrid, 256, AT_SMEM>>>(Qb, Kb, Vb, Ab);

    transpose_cvt<<<tgrid, tblk>>>(W_O, Wt);
    gemm_tn<<<ggrid, 256, GEMM_SMEM>>>(Ab, Wt, out, 0);
}

// round 6
// speedup vs baseline: 9.4804x; 1.0216x over previous
#include <cuda_runtime.h>
#include <cuda.h>
#include <math.h>
#include <stdint.h>

// Problem dims (fixed)
#define BATCH 4
#define SEQ   2048
#define DMOD  1024
#define NHEAD 16
#define HDIM  64
#define MROWS (BATCH*SEQ)   // 8192

// Scratch (device globals; no allocation allowed)
__device__ float g_Q[BATCH*SEQ*DMOD];
__device__ float g_K[BATCH*SEQ*DMOD];
__device__ float g_V[BATCH*SEQ*DMOD];
__device__ float g_A[BATCH*SEQ*DMOD];
__device__ float g_Wt4[4*DMOD*DMOD];    // 4 transposed + tf32-rounded weights

// tcgen05 only exists in the arch-SPECIFIC (sm_103a) compilation pass.
#if defined(__CUDA_ARCH_FEAT_SM103_ALL) || \
    (defined(__CUDA_ARCH_SPECIFIC__) && (__CUDA_ARCH_SPECIFIC__ == 1030)) || \
    defined(__CUDA_ARCH_FEAT_SM100_ALL)
#define USE_TC 1
#else
#define USE_TC 0
#endif

// ---------------------------------------------------------------------------
// Helpers
// ---------------------------------------------------------------------------
__device__ __forceinline__ float cvt_tf32(float x) {
    uint32_t u;
    asm("cvt.rna.tf32.f32 %0, %1;" : "=r"(u) : "f"(x));
    return __uint_as_float(u);
}

#if USE_TC
__device__ __forceinline__ uint32_t smem_u32(const void* p) {
    uint32_t a;
    asm("{ .reg .u64 t; cvta.to.shared.u64 t, %1; cvt.u32.u64 %0, t; }"
        : "=r"(a) : "l"(p));
    return a;
}
__device__ __forceinline__ uint32_t elect_one() {
    uint32_t pred;
    asm volatile("{\n\t.reg .pred p;\n\telect.sync _|p, 0xFFFFFFFF;\n\t"
                 "selp.b32 %0, 1, 0, p;\n\t}" : "=r"(pred));
    return pred;
}

#define CP_ASYNC16(dst, src) \
    asm volatile("cp.async.cg.shared.global [%0], [%1], 16;" \
        :: "r"(dst), "l"(src) : "memory")
#define CP_COMMIT() asm volatile("cp.async.commit_group;" ::: "memory")
#define CP_WAIT0()  asm volatile("cp.async.wait_group 0;" ::: "memory")

#define MBAR_INIT(a, n) \
    asm volatile("mbarrier.init.shared.b64 [%0], %1;" :: "r"(a), "r"(n) : "memory")
#define MBAR_INVAL(a) \
    asm volatile("mbarrier.inval.shared.b64 [%0];" :: "r"(a) : "memory")
#define MBAR_WAIT(a, ph) do {                                                  \
    uint32_t _m = (a), _p = (ph), _d;                                          \
    asm volatile("{\n\t.reg .pred p;\n\t"                                      \
        "mbarrier.try_wait.parity.acquire.cta.shared::cta.b64 p, [%1], %2;\n\t"\
        "selp.b32 %0, 1, 0, p;\n\t}" : "=r"(_d) : "r"(_m), "r"(_p) : "memory");\
    if (!_d) {                                                                 \
        asm volatile("{\n\t.reg .pred P1;\n\tWL_%=:\n\t"                       \
            "mbarrier.try_wait.parity.acquire.cta.shared::cta.b64 P1, [%0], %1, 0x989680;\n\t" \
            "@P1 bra.uni WD_%=;\n\tbra.uni WL_%=;\n\tWD_%=:\n\t}"              \
            :: "r"(_m), "r"(_p) : "memory");                                   \
    }                                                                          \
} while (0)

#define TC_ALLOC(smem_addr, n) \
    asm volatile("tcgen05.alloc.cta_group::1.sync.aligned.shared::cta.b32 [%0], %1;" \
        :: "r"(smem_addr), "r"((uint32_t)(n)) : "memory")
#define TC_DEALLOC(tmem, n) \
    asm volatile("tcgen05.dealloc.cta_group::1.sync.aligned.b32 %0, %1;" \
        :: "r"(tmem), "r"((uint32_t)(n)))
#define TC_RELINQ() \
    asm volatile("tcgen05.relinquish_alloc_permit.cta_group::1.sync.aligned;")
#define TC_COMMIT(mbar) \
    asm volatile("tcgen05.commit.cta_group::1.mbarrier::arrive::one.shared::cluster.b64 [%0];" \
        :: "r"(mbar) : "memory")
#define TC_FENCE_AFTER()  asm volatile("tcgen05.fence::after_thread_sync;" ::: "memory")
#define TC_FENCE_BEFORE() asm volatile("tcgen05.fence::before_thread_sync;" ::: "memory")
#define FENCE_ASYNC_SHARED() asm volatile("fence.proxy.async.shared::cta;" ::: "memory")
#define TC_WAIT_LD() asm volatile("tcgen05.wait::ld.sync.aligned;" ::: "memory")

#define TC_LD_X32(r, tmem) \
    asm volatile("tcgen05.ld.sync.aligned.32x32b.x32.b32 " \
        "{%0,%1,%2,%3,%4,%5,%6,%7,%8,%9,%10,%11,%12,%13,%14,%15," \
        "%16,%17,%18,%19,%20,%21,%22,%23,%24,%25,%26,%27,%28,%29,%30,%31}, [%32];" \
        : "=r"((r)[0]),"=r"((r)[1]),"=r"((r)[2]),"=r"((r)[3]), \
          "=r"((r)[4]),"=r"((r)[5]),"=r"((r)[6]),"=r"((r)[7]), \
          "=r"((r)[8]),"=r"((r)[9]),"=r"((r)[10]),"=r"((r)[11]), \
          "=r"((r)[12]),"=r"((r)[13]),"=r"((r)[14]),"=r"((r)[15]), \
          "=r"((r)[16]),"=r"((r)[17]),"=r"((r)[18]),"=r"((r)[19]), \
          "=r"((r)[20]),"=r"((r)[21]),"=r"((r)[22]),"=r"((r)[23]), \
          "=r"((r)[24]),"=r"((r)[25]),"=r"((r)[26]),"=r"((r)[27]), \
          "=r"((r)[28]),"=r"((r)[29]),"=r"((r)[30]),"=r"((r)[31]) \
        : "r"(tmem))

// SMEM descriptor: SW128, Blackwell, LBO=1, SBO=64 (K-major)
static __device__ __forceinline__ uint64_t make_desc(uint32_t addr) {
    const uint64_t base =
        (uint64_t(2) << 61) | (uint64_t(1) << 46) | (uint64_t(64) << 32) | (uint64_t(1) << 16);
    return base | ((uint64_t)(addr >> 4) & 0x3FFF);
}

__device__ __forceinline__ void mma_tf32_ss(
    uint32_t d, uint64_t ad, uint64_t bd, uint32_t idesc, uint32_t en)
{
    asm volatile("{\n\t.reg .pred p;\n\tsetp.ne.u32 p, %5, 0;\n\t"
        "tcgen05.mma.cta_group::1.kind::tf32 [%0], %1, %2, %3, {%4,%4,%4,%4}, p;\n\t}"
        :: "r"(d), "l"(ad), "l"(bd), "r"(idesc), "r"(0u), "r"(en) : "memory");
}
#define IDESC_N256 0x8400910u
#define IDESC_N128 0x8200910u
#define IDESC_N64  0x8100910u
#endif  // USE_TC

// ---------------------------------------------------------------------------
// GEMM: C[128,256 tile] = A[M,1024] @ Bt^T  (Bt [N,K], pre-rounded tf32)
// A: LDG -> cvt.rna.tf32 -> STS (pipelined one chunk ahead); B: cp.async.
// 2-stage, K-chunk 32.
// ---------------------------------------------------------------------------
#define GK        1024
#define KCHUNK    32
#define NCHUNK    (GK / KCHUNK)
#define STAGE_B   49152                    // 16KB A + 32KB B
#define SM_HDR    1024
#define SM_A(s)   (SM_HDR + (s) * STAGE_B)
#define SM_B(s)   (SM_HDR + (s) * STAGE_B + 16384)
#define GEMM_SMEM (SM_HDR + 2 * STAGE_B)   // 99328

__global__ __launch_bounds__(256)
void gemm_tn(const float* __restrict__ A, const float* __restrict__ Bt,
             float* __restrict__ C, int round_out)
{
    extern __shared__ char smem[];
    const int tid = threadIdx.x;
    const long bm = (long)blockIdx.y * 128;
    const long bn = (long)blockIdx.x * 256;

#if USE_TC
    const uint32_t smem_base = smem_u32(smem);
    const int wid = tid >> 5;
    const int lid = tid & 31;
    const uint32_t mb[2] = {smem_base + 8, smem_base + 16};
    const int r8  = tid >> 3;          // 0..31
    const int kk8 = (tid & 7) * 4;     // 0..28
    const uint32_t swA[4] = {
        ((uint32_t)((0*32 + r8)*128 + kk8*4)) ^ ((((uint32_t)((0*32+r8)*128 + kk8*4)) >> 3) & 0x70),
        ((uint32_t)((1*32 + r8)*128 + kk8*4)) ^ ((((uint32_t)((1*32+r8)*128 + kk8*4)) >> 3) & 0x70),
        ((uint32_t)((2*32 + r8)*128 + kk8*4)) ^ ((((uint32_t)((2*32+r8)*128 + kk8*4)) >> 3) & 0x70),
        ((uint32_t)((3*32 + r8)*128 + kk8*4)) ^ ((((uint32_t)((3*32+r8)*128 + kk8*4)) >> 3) & 0x70)};

    if (wid == 0) { TC_ALLOC(smem_base, 256); TC_RELINQ(); }
    if (tid == 0) { MBAR_INIT(mb[0], 1); MBAR_INIT(mb[1], 1); }
    __syncthreads();
    uint32_t tmem;
    asm volatile("ld.shared.b32 %0, [%1];" : "=r"(tmem) : "r"(smem_base));

    // Prologue: LDG A(0), cp.async B(0) into stage 0
    float4 areg[4];
    #pragma unroll
    for (int p = 0; p < 4; p++)
        areg[p] = *(const float4*)&A[(bm + p*32 + r8) * (long)GK + kk8];
    #pragma unroll
    for (int p = 0; p < 8; p++) {
        int row = p * 32 + r8;
        uint32_t off = (uint32_t)(row * 128 + kk8 * 4);
        uint32_t sw  = off ^ ((off >> 3) & 0x70);
        CP_ASYNC16(smem_base + SM_B(0) + sw, &Bt[(bn + row) * (long)GK + kk8]);
    }
    CP_COMMIT();

    uint32_t ph[2] = {0, 0};

    for (int c = 0; c < NCHUNK; c++) {
        const int s = c & 1;
        // STS A(c) (rounded) into stage s
        {
            char* sA = smem + SM_A(s);
            #pragma unroll
            for (int p = 0; p < 4; p++)
                *(float4*)(sA + swA[p]) = make_float4(
                    cvt_tf32(areg[p].x), cvt_tf32(areg[p].y),
                    cvt_tf32(areg[p].z), cvt_tf32(areg[p].w));
        }
        CP_WAIT0();        // B(c) resident
        __syncthreads();

        if (wid == 0 && elect_one()) {
            FENCE_ASYNC_SHARED();
            uint64_t ad = make_desc(smem_base + SM_A(s));
            uint64_t bd = make_desc(smem_base + SM_B(s));
            #pragma unroll
            for (int k = 0; k < 4; k++)
                mma_tf32_ss(tmem, ad + k * 2, bd + k * 2, IDESC_N256,
                            (c > 0) | (k > 0));
            TC_COMMIT(mb[s]);
        }

        if (c + 1 < NCHUNK) {
            const int ns = s ^ 1;
            const int k0 = (c + 1) * KCHUNK;
            if (c >= 1) { MBAR_WAIT(mb[ns], ph[ns]); ph[ns] ^= 1; }
            #pragma unroll
            for (int p = 0; p < 4; p++)
                areg[p] = *(const float4*)&A[(bm + p*32 + r8) * (long)GK + k0 + kk8];
            #pragma unroll
            for (int p = 0; p < 8; p++) {
                int row = p * 32 + r8;
                uint32_t off = (uint32_t)(row * 128 + kk8 * 4);
                uint32_t sw  = off ^ ((off >> 3) & 0x70);
                CP_ASYNC16(smem_base + SM_B(ns) + sw,
                           &Bt[(bn + row) * (long)GK + k0 + kk8]);
            }
            CP_COMMIT();
        }
    }
    {
        const int ls = (NCHUNK - 1) & 1;
        MBAR_WAIT(mb[ls], ph[ls]); ph[ls] ^= 1;
    }
    TC_FENCE_AFTER();

    if (wid < 4) {
        const long row = bm + wid * 32 + lid;
        float* crow = &C[row * (long)GK + bn];
        #pragma unroll
        for (int nb = 0; nb < 8; nb++) {
            uint32_t r[32];
            TC_LD_X32(r, tmem + nb * 32);
            TC_WAIT_LD();
            if (round_out) {
                #pragma unroll
                for (int j = 0; j < 8; j++)
                    *(float4*)&crow[nb * 32 + j * 4] = make_float4(
                        cvt_tf32(__uint_as_float(r[j*4+0])), cvt_tf32(__uint_as_float(r[j*4+1])),
                        cvt_tf32(__uint_as_float(r[j*4+2])), cvt_tf32(__uint_as_float(r[j*4+3])));
            } else {
                #pragma unroll
                for (int j = 0; j < 8; j++)
                    *(float4*)&crow[nb * 32 + j * 4] = make_float4(
                        __uint_as_float(r[j*4+0]), __uint_as_float(r[j*4+1]),
                        __uint_as_float(r[j*4+2]), __uint_as_float(r[j*4+3]));
            }
        }
        TC_FENCE_BEFORE();
    }
    __syncthreads();
    if (tid == 0) { MBAR_INVAL(mb[0]); MBAR_INVAL(mb[1]); }
    if (wid == 0) TC_DEALLOC(tmem, 256);

#else  // SIMT fallback (two 128-wide N halves)
    float* As = (float*)smem;
    float* Bs = (float*)smem + 16 * 128;
    const int tx = tid & 15, ty = tid >> 4;
    const int ar = tid >> 2, ak = (tid & 3) * 4;
    for (int half = 0; half < 2; half++) {
        const long bn2 = bn + half * 128;
        float acc[8][8];
        #pragma unroll
        for (int i = 0; i < 8; i++)
            #pragma unroll
            for (int j = 0; j < 8; j++) acc[i][j] = 0.f;
        for (int k0 = 0; k0 < GK; k0 += 16) {
            float4 a0 = *(const float4*)&A [(bm + ar)      * (long)GK + k0 + ak];
            float4 a1 = *(const float4*)&A [(bm + ar + 64) * (long)GK + k0 + ak];
            float4 b0 = *(const float4*)&Bt[(bn2 + ar)      * (long)GK + k0 + ak];
            float4 b1 = *(const float4*)&Bt[(bn2 + ar + 64) * (long)GK + k0 + ak];
            As[(ak+0)*128+ar]=cvt_tf32(a0.x); As[(ak+1)*128+ar]=cvt_tf32(a0.y);
            As[(ak+2)*128+ar]=cvt_tf32(a0.z); As[(ak+3)*128+ar]=cvt_tf32(a0.w);
            As[(ak+0)*128+ar+64]=cvt_tf32(a1.x); As[(ak+1)*128+ar+64]=cvt_tf32(a1.y);
            As[(ak+2)*128+ar+64]=cvt_tf32(a1.z); As[(ak+3)*128+ar+64]=cvt_tf32(a1.w);
            Bs[(ak+0)*128+ar]=b0.x; Bs[(ak+1)*128+ar]=b0.y; Bs[(ak+2)*128+ar]=b0.z; Bs[(ak+3)*128+ar]=b0.w;
            Bs[(ak+0)*128+ar+64]=b1.x; Bs[(ak+1)*128+ar+64]=b1.y; Bs[(ak+2)*128+ar+64]=b1.z; Bs[(ak+3)*128+ar+64]=b1.w;
            __syncthreads();
            #pragma unroll
            for (int kk = 0; kk < 16; kk++) {
                float ra[8], rb[8];
                *(float4*)&ra[0] = *(const float4*)&As[kk*128+ty*8];
                *(float4*)&ra[4] = *(const float4*)&As[kk*128+ty*8+4];
                *(float4*)&rb[0] = *(const float4*)&Bs[kk*128+tx*8];
                *(float4*)&rb[4] = *(const float4*)&Bs[kk*128+tx*8+4];
                #pragma unroll
                for (int i = 0; i < 8; i++)
                    #pragma unroll
                    for (int j = 0; j < 8; j++)
                        acc[i][j] = fmaf(ra[i], rb[j], acc[i][j]);
            }
            __syncthreads();
        }
        #pragma unroll
        for (int i = 0; i < 8; i++) {
            long row = (bm + ty*8 + i) * (long)GK + bn2 + tx*8;
            *(float4*)&C[row]   = make_float4(acc[i][0],acc[i][1],acc[i][2],acc[i][3]);
            *(float4*)&C[row+4] = make_float4(acc[i][4],acc[i][5],acc[i][6],acc[i][7]);
        }
    }
#endif
}

// ---------------------------------------------------------------------------
// Fused transpose + tf32-round for all 4 weights (grid.z picks the weight)
// ---------------------------------------------------------------------------
__global__ __launch_bounds__(256) void transpose_cvt4(
    const float* __restrict__ W0, const float* __restrict__ W1,
    const float* __restrict__ W2, const float* __restrict__ W3,
    float* __restrict__ Wt)
{
    __shared__ float t[32][33];
    const float* W = (blockIdx.z == 0) ? W0 : (blockIdx.z == 1) ? W1
                   : (blockIdx.z == 2) ? W2 : W3;
    float* T = Wt + (long)blockIdx.z * DMOD * DMOD;
    const int tx = threadIdx.x, ty = threadIdx.y;
    const int n0 = blockIdx.x * 32, k0 = blockIdx.y * 32;
    #pragma unroll
    for (int i = 0; i < 4; i++)
        t[ty + 8*i][tx] = W[(long)(k0 + ty + 8*i) * DMOD + n0 + tx];
    __syncthreads();
    #pragma unroll
    for (int i = 0; i < 4; i++)
        T[(long)(n0 + ty + 8*i) * DMOD + k0 + tx] = cvt_tf32(t[tx][ty + 8*i]);
}

// ---------------------------------------------------------------------------
// tcgen05 flash attention (causal) — unchanged from R5
// ---------------------------------------------------------------------------
#define AT_SQ    3072
#define AT_SK    (AT_SQ + 32768)
#define AT_SV    (AT_SK + 65536)
#define AT_SP    (AT_SV + 32768)
#define AT_SMEM  (AT_SP + 65536)           // 199680

__global__ __launch_bounds__(256)
void flash_attn_tc(const float* __restrict__ Qg, const float* __restrict__ Kg,
                   const float* __restrict__ Vg, float* __restrict__ Og)
{
    extern __shared__ char smem[];
    const int tid = threadIdx.x;
    const int qx = blockIdx.x, h = blockIdx.y, b = blockIdx.z;

#if USE_TC
    const uint32_t smem_base = smem_u32(smem);
    const int wid = tid >> 5;
    const int lid = tid & 31;
    const int wg  = wid >> 2;
    const int row = (wid & 3) * 32 + lid;
    const uint32_t mb_s = smem_base + 16;
    const uint32_t mb_o = smem_base + 32;
    float* red_m = (float*)(smem + 1024);
    float* red_s = (float*)(smem + 2048);

    if (wid == 0) { TC_ALLOC(smem_base, 256); TC_RELINQ(); }
    if (tid == 0) { MBAR_INIT(mb_s, 1); MBAR_INIT(mb_o, 1); }
    __syncthreads();
    uint32_t tmem;
    asm volatile("ld.shared.b32 %0, [%1];" : "=r"(tmem) : "r"(smem_base));
    const uint32_t tmem_S = tmem;
    const uint32_t tmem_O = tmem + 128;

    const long rowbase = (long)(b * SEQ) * DMOD + h * 64;
    const int q0 = qx * 128;
    const int r8  = tid >> 3;
    const int kk8 = (tid & 7) * 4;

    #pragma unroll
    for (int s = 0; s < 2; s++)
        #pragma unroll
        for (int p = 0; p < 4; p++) {
            int rr = p * 32 + r8;
            uint32_t off = (uint32_t)(rr * 128 + kk8 * 4);
            uint32_t sw  = off ^ ((off >> 3) & 0x70);
            CP_ASYNC16(smem_base + AT_SQ + s*16384 + sw,
                       &Qg[rowbase + (long)(q0 + rr) * DMOD + s*32 + kk8]);
        }
    CP_COMMIT();
    #pragma unroll
    for (int s = 0; s < 2; s++)
        #pragma unroll
        for (int p = 0; p < 4; p++) {
            int rr = p * 32 + r8;
            uint32_t off = (uint32_t)(rr * 128 + kk8 * 4);
            uint32_t sw  = off ^ ((off >> 3) & 0x70);
            CP_ASYNC16(smem_base + AT_SK + s*16384 + sw,
                       &Kg[rowbase + (long)rr * DMOD + s*32 + kk8]);
        }
    CP_COMMIT();

    const int cbase = wg * 64;
    const int row_g = q0 + row;
    float mrow = -1e30f, lrow = 0.f, alpha_prev = 1.f;
    float acc[32];
    #pragma unroll
    for (int j = 0; j < 32; j++) acc[j] = 0.f;
    uint32_t ph_s = 0, ph_o = 0;
    const float scaling = 0.125f;

    CP_WAIT0();
    __syncthreads();

    for (int kt = 0; kt <= qx; kt++) {
        const int kb = kt & 1;
        const int k0 = kt * 128;

        if (wid == 0 && elect_one()) {
            FENCE_ASYNC_SHARED();
            TC_FENCE_AFTER();
            #pragma unroll
            for (int s = 0; s < 2; s++) {
                uint64_t qd = make_desc(smem_base + AT_SQ + s*16384);
                uint64_t kd = make_desc(smem_base + AT_SK + kb*32768 + s*16384);
                #pragma unroll
                for (int k = 0; k < 4; k++)
                    mma_tf32_ss(tmem_S, qd + k*2, kd + k*2, IDESC_N128, (s|k) != 0);
            }
            TC_COMMIT(mb_s);
        }

        if (kt < qx) {
            const int nk0 = k0 + 128;
            #pragma unroll
            for (int s = 0; s < 2; s++)
                #pragma unroll
                for (int p = 0; p < 4; p++) {
                    int rr = p * 32 + r8;
                    uint32_t off = (uint32_t)(rr * 128 + kk8 * 4);
                    uint32_t sw  = off ^ ((off >> 3) & 0x70);
                    CP_ASYNC16(smem_base + AT_SK + (kb^1)*32768 + s*16384 + sw,
                               &Kg[rowbase + (long)(nk0 + rr) * DMOD + s*32 + kk8]);
                }
            CP_COMMIT();
        }

        if (kt > 0) {
            MBAR_WAIT(mb_o, ph_o); ph_o ^= 1;
            TC_FENCE_AFTER();
            uint32_t du[32];
            TC_LD_X32(du, tmem_O + wg * 32);
            TC_WAIT_LD();
            TC_FENCE_BEFORE();
            #pragma unroll
            for (int j = 0; j < 32; j++)
                acc[j] = acc[j] * alpha_prev + __uint_as_float(du[j]);
        }

        {
            const int dv4 = (tid & 15) * 4;
            const int kv0 = tid >> 4;
            #pragma unroll
            for (int it = 0; it < 8; it++) {
                int kv = kv0 + it * 16;
                float4 v = *(const float4*)&Vg[rowbase + (long)(k0 + kv) * DMOD + dv4];
                char* basep = smem + AT_SV + (kv >> 5) * 8192;
                int within = kv & 31;
                float vv[4] = {v.x, v.y, v.z, v.w};
                #pragma unroll
                for (int j = 0; j < 4; j++) {
                    uint32_t off = (uint32_t)((dv4 + j) * 128 + within * 4);
                    uint32_t sw  = off ^ ((off >> 3) & 0x70);
                    *(float*)(basep + sw) = vv[j];
                }
            }
        }

        MBAR_WAIT(mb_s, ph_s); ph_s ^= 1;
        TC_FENCE_AFTER();
        uint32_t u0[32], u1[32];
        TC_LD_X32(u0, tmem_S + cbase);
        TC_LD_X32(u1, tmem_S + cbase + 32);
        TC_WAIT_LD();
        TC_FENCE_BEFORE();

        float sv[64];
        #pragma unroll
        for (int j = 0; j < 32; j++) {
            sv[j]      = __uint_as_float(u0[j]) * scaling;
            sv[32 + j] = __uint_as_float(u1[j]) * scaling;
        }
        if (kt == qx) {
            #pragma unroll
            for (int j = 0; j < 64; j++)
                if (k0 + cbase + j > row_g) sv[j] = -1e30f;
        }

        float lm = sv[0];
        #pragma unroll
        for (int j = 1; j < 64; j++) lm = fmaxf(lm, sv[j]);
        red_m[wg * 128 + row] = lm;
        __syncthreads();
        float mtile = fmaxf(red_m[row], red_m[128 + row]);
        float mnew  = fmaxf(mrow, mtile);
        float alpha = __expf(mrow - mnew);

        float ls = 0.f;
        #pragma unroll
        for (int j = 0; j < 64; j++) {
            float p = __expf(sv[j] - mnew);
            sv[j] = p;
            ls += p;
        }
        red_s[wg * 128 + row] = ls;

        #pragma unroll
        for (int g = 0; g < 16; g++) {
            int c = cbase + g * 4;
            char* basep = smem + AT_SP + (c >> 5) * 16384;
            uint32_t off = (uint32_t)(row * 128 + (c & 31) * 4);
            uint32_t sw  = off ^ ((off >> 3) & 0x70);
            *(float4*)(basep + sw) = make_float4(
                cvt_tf32(sv[g*4+0]), cvt_tf32(sv[g*4+1]),
                cvt_tf32(sv[g*4+2]), cvt_tf32(sv[g*4+3]));
        }

        CP_WAIT0();
        __syncthreads();

        float ltile = red_s[row] + red_s[128 + row];
        lrow = lrow * alpha + ltile;
        mrow = mnew;
        alpha_prev = alpha;

        if (wid == 0 && elect_one()) {
            FENCE_ASYNC_SHARED();
            TC_FENCE_AFTER();
            #pragma unroll
            for (int c = 0; c < 4; c++) {
                uint64_t pd = make_desc(smem_base + AT_SP + c*16384);
                uint64_t vd = make_desc(smem_base + AT_SV + c*8192);
                #pragma unroll
                for (int k = 0; k < 4; k++)
                    mma_tf32_ss(tmem_O, pd + k*2, vd + k*2, IDESC_N64, (c|k) != 0);
            }
            TC_COMMIT(mb_o);
        }
    }

    MBAR_WAIT(mb_o, ph_o); ph_o ^= 1;
    TC_FENCE_AFTER();
    {
        uint32_t du[32];
        TC_LD_X32(du, tmem_O + wg * 32);
        TC_WAIT_LD();
        TC_FENCE_BEFORE();
        #pragma unroll
        for (int j = 0; j < 32; j++)
            acc[j] = acc[j] * alpha_prev + __uint_as_float(du[j]);

        float inv = 1.f / lrow;
        float* orow = &Og[rowbase + (long)(q0 + row) * DMOD + wg * 32];
        #pragma unroll
        for (int g = 0; g < 8; g++)
            *(float4*)&orow[g * 4] = make_float4(
                acc[g*4+0]*inv, acc[g*4+1]*inv,
                acc[g*4+2]*inv, acc[g*4+3]*inv);
    }
    __syncthreads();
    if (tid == 0) { MBAR_INVAL(mb_s); MBAR_INVAL(mb_o); }
    if (wid == 0) TC_DEALLOC(tmem, 256);

#else  // trivial fallback
    if (tid < 128) {
        const long rowbase = (long)(b * SEQ) * DMOD + h * 64;
        const int q = qx * 128 + tid;
        float qreg[64];
        #pragma unroll
        for (int d = 0; d < 64; d++) qreg[d] = Qg[rowbase + (long)q * DMOD + d];
        float m = -1e30f, l = 0.f, acc[64];
        #pragma unroll
        for (int d = 0; d < 64; d++) acc[d] = 0.f;
        for (int kv = 0; kv <= q; kv++) {
            const float* kr = &Kg[rowbase + (long)kv * DMOD];
            float s = 0.f;
            for (int d = 0; d < 64; d++) s += qreg[d] * kr[d];
            s *= 0.125f;
            float mn = fmaxf(m, s);
            float al = __expf(m - mn), p = __expf(s - mn);
            l = l * al + p;
            const float* vr = &Vg[rowbase + (long)kv * DMOD];
            for (int d = 0; d < 64; d++) acc[d] = acc[d] * al + p * vr[d];
            m = mn;
        }
        float inv = 1.f / l;
        for (int d = 0; d < 64; d++)
            Og[rowbase + (long)q * DMOD + d] = acc[d] * inv;
    }
#endif
}

// ---------------------------------------------------------------------------
// Host launcher
// ---------------------------------------------------------------------------
extern "C" void kernel_launch(void* const* d_in, const int* in_sizes, int n_in,
                              void* d_out, int out_size)
{
    const float* queries = (const float*)d_in[0];
    const float* keys    = (const float*)d_in[1];
    const float* values  = (const float*)d_in[2];
    // d_in[3] = mask — causal, analytic
    const float* W_Q = (const float*)d_in[4];
    const float* W_K = (const float*)d_in[5];
    const float* W_V = (const float*)d_in[6];
    const float* W_O = (const float*)d_in[7];
    float* out = (float*)d_out;

    float *Qb, *Kb, *Vb, *Ab, *Wt;
    cudaGetSymbolAddress((void**)&Qb, g_Q);
    cudaGetSymbolAddress((void**)&Kb, g_K);
    cudaGetSymbolAddress((void**)&Vb, g_V);
    cudaGetSymbolAddress((void**)&Ab, g_A);
    cudaGetSymbolAddress((void**)&Wt, g_Wt4);

    cudaFuncSetAttribute(gemm_tn, cudaFuncAttributeMaxDynamicSharedMemorySize,
                         GEMM_SMEM);
    cudaFuncSetAttribute(flash_attn_tc, cudaFuncAttributeMaxDynamicSharedMemorySize,
                         AT_SMEM);

    const long WSZ = (long)DMOD * DMOD;
    dim3 tgrid(32, 32, 4), tblk(32, 8);
    dim3 ggrid(DMOD / 256, MROWS / 128);   // (4, 64)

    transpose_cvt4<<<tgrid, tblk>>>(W_Q, W_K, W_V, W_O, Wt);

    gemm_tn<<<ggrid, 256, GEMM_SMEM>>>(queries, Wt + 0*WSZ, Qb, 1);
    gemm_tn<<<ggrid, 256, GEMM_SMEM>>>(keys,    Wt + 1*WSZ, Kb, 1);
    gemm_tn<<<ggrid, 256, GEMM_SMEM>>>(values,  Wt + 2*WSZ, Vb, 1);

    dim3 agrid(SEQ / 128, NHEAD, BATCH);
    flash_attn_tc<<<agrid, 256, AT_SMEM>>>(Qb, Kb, Vb, Ab);

    gemm_tn<<<ggrid, 256, GEMM_SMEM>>>(Ab, Wt + 3*WSZ, out, 0);
}

// round 7
// speedup vs baseline: 9.5598x; 1.0084x over previous
#include <cuda_runtime.h>
#include <cuda.h>
#include <math.h>
#include <stdint.h>

// Problem dims (fixed)
#define BATCH 4
#define SEQ   2048
#define DMOD  1024
#define NHEAD 16
#define HDIM  64
#define MROWS (BATCH*SEQ)   // 8192

// Scratch (device globals; no allocation allowed)
__device__ float g_Q[BATCH*SEQ*DMOD];
__device__ float g_K[BATCH*SEQ*DMOD];
__device__ float g_V[BATCH*SEQ*DMOD];
__device__ float g_A[BATCH*SEQ*DMOD];
__device__ float g_Wt4[4*DMOD*DMOD];    // 4 transposed + tf32-rounded weights

// tcgen05 only exists in the arch-SPECIFIC (sm_103a) compilation pass.
#if defined(__CUDA_ARCH_FEAT_SM103_ALL) || \
    (defined(__CUDA_ARCH_SPECIFIC__) && (__CUDA_ARCH_SPECIFIC__ == 1030)) || \
    defined(__CUDA_ARCH_FEAT_SM100_ALL)
#define USE_TC 1
#else
#define USE_TC 0
#endif

// ---------------------------------------------------------------------------
// Helpers
// ---------------------------------------------------------------------------
__device__ __forceinline__ float cvt_tf32(float x) {
    uint32_t u;
    asm("cvt.rna.tf32.f32 %0, %1;" : "=r"(u) : "f"(x));
    return __uint_as_float(u);
}

#if USE_TC
__device__ __forceinline__ uint32_t smem_u32(const void* p) {
    uint32_t a;
    asm("{ .reg .u64 t; cvta.to.shared.u64 t, %1; cvt.u32.u64 %0, t; }"
        : "=r"(a) : "l"(p));
    return a;
}
__device__ __forceinline__ uint32_t elect_one() {
    uint32_t pred;
    asm volatile("{\n\t.reg .pred p;\n\telect.sync _|p, 0xFFFFFFFF;\n\t"
                 "selp.b32 %0, 1, 0, p;\n\t}" : "=r"(pred));
    return pred;
}

#define CP_ASYNC16(dst, src) \
    asm volatile("cp.async.cg.shared.global [%0], [%1], 16;" \
        :: "r"(dst), "l"(src) : "memory")
#define CP_COMMIT() asm volatile("cp.async.commit_group;" ::: "memory")
#define CP_WAIT0()  asm volatile("cp.async.wait_group 0;" ::: "memory")

#define MBAR_INIT(a, n) \
    asm volatile("mbarrier.init.shared.b64 [%0], %1;" :: "r"(a), "r"(n) : "memory")
#define MBAR_INVAL(a) \
    asm volatile("mbarrier.inval.shared.b64 [%0];" :: "r"(a) : "memory")
#define MBAR_WAIT(a, ph) do {                                                  \
    uint32_t _m = (a), _p = (ph), _d;                                          \
    asm volatile("{\n\t.reg .pred p;\n\t"                                      \
        "mbarrier.try_wait.parity.acquire.cta.shared::cta.b64 p, [%1], %2;\n\t"\
        "selp.b32 %0, 1, 0, p;\n\t}" : "=r"(_d) : "r"(_m), "r"(_p) : "memory");\
    if (!_d) {                                                                 \
        asm volatile("{\n\t.reg .pred P1;\n\tWL_%=:\n\t"                       \
            "mbarrier.try_wait.parity.acquire.cta.shared::cta.b64 P1, [%0], %1, 0x989680;\n\t" \
            "@P1 bra.uni WD_%=;\n\tbra.uni WL_%=;\n\tWD_%=:\n\t}"              \
            :: "r"(_m), "r"(_p) : "memory");                                   \
    }                                                                          \
} while (0)

#define TC_ALLOC(smem_addr, n) \
    asm volatile("tcgen05.alloc.cta_group::1.sync.aligned.shared::cta.b32 [%0], %1;" \
        :: "r"(smem_addr), "r"((uint32_t)(n)) : "memory")
#define TC_DEALLOC(tmem, n) \
    asm volatile("tcgen05.dealloc.cta_group::1.sync.aligned.b32 %0, %1;" \
        :: "r"(tmem), "r"((uint32_t)(n)))
#define TC_RELINQ() \
    asm volatile("tcgen05.relinquish_alloc_permit.cta_group::1.sync.aligned;")
#define TC_COMMIT(mbar) \
    asm volatile("tcgen05.commit.cta_group::1.mbarrier::arrive::one.shared::cluster.b64 [%0];" \
        :: "r"(mbar) : "memory")
#define TC_FENCE_AFTER()  asm volatile("tcgen05.fence::after_thread_sync;" ::: "memory")
#define TC_FENCE_BEFORE() asm volatile("tcgen05.fence::before_thread_sync;" ::: "memory")
#define FENCE_ASYNC_SHARED() asm volatile("fence.proxy.async.shared::cta;" ::: "memory")
#define TC_WAIT_LD() asm volatile("tcgen05.wait::ld.sync.aligned;" ::: "memory")

#define TC_LD_X32(r, tmem) \
    asm volatile("tcgen05.ld.sync.aligned.32x32b.x32.b32 " \
        "{%0,%1,%2,%3,%4,%5,%6,%7,%8,%9,%10,%11,%12,%13,%14,%15," \
        "%16,%17,%18,%19,%20,%21,%22,%23,%24,%25,%26,%27,%28,%29,%30,%31}, [%32];" \
        : "=r"((r)[0]),"=r"((r)[1]),"=r"((r)[2]),"=r"((r)[3]), \
          "=r"((r)[4]),"=r"((r)[5]),"=r"((r)[6]),"=r"((r)[7]), \
          "=r"((r)[8]),"=r"((r)[9]),"=r"((r)[10]),"=r"((r)[11]), \
          "=r"((r)[12]),"=r"((r)[13]),"=r"((r)[14]),"=r"((r)[15]), \
          "=r"((r)[16]),"=r"((r)[17]),"=r"((r)[18]),"=r"((r)[19]), \
          "=r"((r)[20]),"=r"((r)[21]),"=r"((r)[22]),"=r"((r)[23]), \
          "=r"((r)[24]),"=r"((r)[25]),"=r"((r)[26]),"=r"((r)[27]), \
          "=r"((r)[28]),"=r"((r)[29]),"=r"((r)[30]),"=r"((r)[31]) \
        : "r"(tmem))

// SMEM descriptor: SW128, Blackwell, LBO=1, SBO=64 (K-major)
static __device__ __forceinline__ uint64_t make_desc(uint32_t addr) {
    const uint64_t base =
        (uint64_t(2) << 61) | (uint64_t(1) << 46) | (uint64_t(64) << 32) | (uint64_t(1) << 16);
    return base | ((uint64_t)(addr >> 4) & 0x3FFF);
}

__device__ __forceinline__ void mma_tf32_ss(
    uint32_t d, uint64_t ad, uint64_t bd, uint32_t idesc, uint32_t en)
{
    asm volatile("{\n\t.reg .pred p;\n\tsetp.ne.u32 p, %5, 0;\n\t"
        "tcgen05.mma.cta_group::1.kind::tf32 [%0], %1, %2, %3, {%4,%4,%4,%4}, p;\n\t}"
        :: "r"(d), "l"(ad), "l"(bd), "r"(idesc), "r"(0u), "r"(en) : "memory");
}
#define IDESC_N256 0x8400910u
#define IDESC_N128 0x8200910u
#define IDESC_N64  0x8100910u
#endif  // USE_TC

// ---------------------------------------------------------------------------
// GEMM: C[128,256 tile] = A[M,1024] @ Bt^T  (Bt [N,K], pre-rounded tf32)
// A: LDG -> cvt.rna.tf32 -> STS (pipelined one chunk ahead); B: cp.async.
// 2-stage, K-chunk 32.
// ---------------------------------------------------------------------------
#define GK        1024
#define KCHUNK    32
#define NCHUNK    (GK / KCHUNK)
#define STAGE_B   49152                    // 16KB A + 32KB B
#define SM_HDR    1024
#define SM_A(s)   (SM_HDR + (s) * STAGE_B)
#define SM_B(s)   (SM_HDR + (s) * STAGE_B + 16384)
#define GEMM_SMEM (SM_HDR + 2 * STAGE_B)   // 99328

__global__ __launch_bounds__(256)
void gemm_tn(const float* __restrict__ A, const float* __restrict__ Bt,
             float* __restrict__ C, int round_out)
{
    extern __shared__ char smem[];
    const int tid = threadIdx.x;
    const long bm = (long)blockIdx.y * 128;
    const long bn = (long)blockIdx.x * 256;

#if USE_TC
    const uint32_t smem_base = smem_u32(smem);
    const int wid = tid >> 5;
    const int lid = tid & 31;
    const uint32_t mb[2] = {smem_base + 8, smem_base + 16};
    const int r8  = tid >> 3;          // 0..31
    const int kk8 = (tid & 7) * 4;     // 0..28
    const uint32_t swA[4] = {
        ((uint32_t)((0*32 + r8)*128 + kk8*4)) ^ ((((uint32_t)((0*32+r8)*128 + kk8*4)) >> 3) & 0x70),
        ((uint32_t)((1*32 + r8)*128 + kk8*4)) ^ ((((uint32_t)((1*32+r8)*128 + kk8*4)) >> 3) & 0x70),
        ((uint32_t)((2*32 + r8)*128 + kk8*4)) ^ ((((uint32_t)((2*32+r8)*128 + kk8*4)) >> 3) & 0x70),
        ((uint32_t)((3*32 + r8)*128 + kk8*4)) ^ ((((uint32_t)((3*32+r8)*128 + kk8*4)) >> 3) & 0x70)};

    if (wid == 0) { TC_ALLOC(smem_base, 256); TC_RELINQ(); }
    if (tid == 0) { MBAR_INIT(mb[0], 1); MBAR_INIT(mb[1], 1); }
    __syncthreads();
    uint32_t tmem;
    asm volatile("ld.shared.b32 %0, [%1];" : "=r"(tmem) : "r"(smem_base));

    // Prologue: LDG A(0), cp.async B(0) into stage 0
    float4 areg[4];
    #pragma unroll
    for (int p = 0; p < 4; p++)
        areg[p] = *(const float4*)&A[(bm + p*32 + r8) * (long)GK + kk8];
    #pragma unroll
    for (int p = 0; p < 8; p++) {
        int row = p * 32 + r8;
        uint32_t off = (uint32_t)(row * 128 + kk8 * 4);
        uint32_t sw  = off ^ ((off >> 3) & 0x70);
        CP_ASYNC16(smem_base + SM_B(0) + sw, &Bt[(bn + row) * (long)GK + kk8]);
    }
    CP_COMMIT();

    uint32_t ph[2] = {0, 0};

    for (int c = 0; c < NCHUNK; c++) {
        const int s = c & 1;
        // STS A(c) (rounded) into stage s
        {
            char* sA = smem + SM_A(s);
            #pragma unroll
            for (int p = 0; p < 4; p++)
                *(float4*)(sA + swA[p]) = make_float4(
                    cvt_tf32(areg[p].x), cvt_tf32(areg[p].y),
                    cvt_tf32(areg[p].z), cvt_tf32(areg[p].w));
        }
        CP_WAIT0();        // B(c) resident
        __syncthreads();

        if (wid == 0 && elect_one()) {
            FENCE_ASYNC_SHARED();
            uint64_t ad = make_desc(smem_base + SM_A(s));
            uint64_t bd = make_desc(smem_base + SM_B(s));
            #pragma unroll
            for (int k = 0; k < 4; k++)
                mma_tf32_ss(tmem, ad + k * 2, bd + k * 2, IDESC_N256,
                            (c > 0) | (k > 0));
            TC_COMMIT(mb[s]);
        }

        if (c + 1 < NCHUNK) {
            const int ns = s ^ 1;
            const int k0 = (c + 1) * KCHUNK;
            if (c >= 1) { MBAR_WAIT(mb[ns], ph[ns]); ph[ns] ^= 1; }
            #pragma unroll
            for (int p = 0; p < 4; p++)
                areg[p] = *(const float4*)&A[(bm + p*32 + r8) * (long)GK + k0 + kk8];
            #pragma unroll
            for (int p = 0; p < 8; p++) {
                int row = p * 32 + r8;
                uint32_t off = (uint32_t)(row * 128 + kk8 * 4);
                uint32_t sw  = off ^ ((off >> 3) & 0x70);
                CP_ASYNC16(smem_base + SM_B(ns) + sw,
                           &Bt[(bn + row) * (long)GK + k0 + kk8]);
            }
            CP_COMMIT();
        }
    }
    {
        const int ls = (NCHUNK - 1) & 1;
        MBAR_WAIT(mb[ls], ph[ls]); ph[ls] ^= 1;
    }
    TC_FENCE_AFTER();

    if (wid < 4) {
        const long row = bm + wid * 32 + lid;
        float* crow = &C[row * (long)GK + bn];
        #pragma unroll
        for (int nb = 0; nb < 8; nb++) {
            uint32_t r[32];
            TC_LD_X32(r, tmem + nb * 32);
            TC_WAIT_LD();
            if (round_out) {
                #pragma unroll
                for (int j = 0; j < 8; j++)
                    *(float4*)&crow[nb * 32 + j * 4] = make_float4(
                        cvt_tf32(__uint_as_float(r[j*4+0])), cvt_tf32(__uint_as_float(r[j*4+1])),
                        cvt_tf32(__uint_as_float(r[j*4+2])), cvt_tf32(__uint_as_float(r[j*4+3])));
            } else {
                #pragma unroll
                for (int j = 0; j < 8; j++)
                    *(float4*)&crow[nb * 32 + j * 4] = make_float4(
                        __uint_as_float(r[j*4+0]), __uint_as_float(r[j*4+1]),
                        __uint_as_float(r[j*4+2]), __uint_as_float(r[j*4+3]));
            }
        }
        TC_FENCE_BEFORE();
    }
    __syncthreads();
    if (tid == 0) { MBAR_INVAL(mb[0]); MBAR_INVAL(mb[1]); }
    if (wid == 0) TC_DEALLOC(tmem, 256);

#else  // SIMT fallback (two 128-wide N halves)
    float* As = (float*)smem;
    float* Bs = (float*)smem + 16 * 128;
    const int tx = tid & 15, ty = tid >> 4;
    const int ar = tid >> 2, ak = (tid & 3) * 4;
    for (int half = 0; half < 2; half++) {
        const long bn2 = bn + half * 128;
        float acc[8][8];
        #pragma unroll
        for (int i = 0; i < 8; i++)
            #pragma unroll
            for (int j = 0; j < 8; j++) acc[i][j] = 0.f;
        for (int k0 = 0; k0 < GK; k0 += 16) {
            float4 a0 = *(const float4*)&A [(bm + ar)      * (long)GK + k0 + ak];
            float4 a1 = *(const float4*)&A [(bm + ar + 64) * (long)GK + k0 + ak];
            float4 b0 = *(const float4*)&Bt[(bn2 + ar)      * (long)GK + k0 + ak];
            float4 b1 = *(const float4*)&Bt[(bn2 + ar + 64) * (long)GK + k0 + ak];
            As[(ak+0)*128+ar]=cvt_tf32(a0.x); As[(ak+1)*128+ar]=cvt_tf32(a0.y);
            As[(ak+2)*128+ar]=cvt_tf32(a0.z); As[(ak+3)*128+ar]=cvt_tf32(a0.w);
            As[(ak+0)*128+ar+64]=cvt_tf32(a1.x); As[(ak+1)*128+ar+64]=cvt_tf32(a1.y);
            As[(ak+2)*128+ar+64]=cvt_tf32(a1.z); As[(ak+3)*128+ar+64]=cvt_tf32(a1.w);
            Bs[(ak+0)*128+ar]=b0.x; Bs[(ak+1)*128+ar]=b0.y; Bs[(ak+2)*128+ar]=b0.z; Bs[(ak+3)*128+ar]=b0.w;
            Bs[(ak+0)*128+ar+64]=b1.x; Bs[(ak+1)*128+ar+64]=b1.y; Bs[(ak+2)*128+ar+64]=b1.z; Bs[(ak+3)*128+ar+64]=b1.w;
            __syncthreads();
            #pragma unroll
            for (int kk = 0; kk < 16; kk++) {
                float ra[8], rb[8];
                *(float4*)&ra[0] = *(const float4*)&As[kk*128+ty*8];
                *(float4*)&ra[4] = *(const float4*)&As[kk*128+ty*8+4];
                *(float4*)&rb[0] = *(const float4*)&Bs[kk*128+tx*8];
                *(float4*)&rb[4] = *(const float4*)&Bs[kk*128+tx*8+4];
                #pragma unroll
                for (int i = 0; i < 8; i++)
                    #pragma unroll
                    for (int j = 0; j < 8; j++)
                        acc[i][j] = fmaf(ra[i], rb[j], acc[i][j]);
            }
            __syncthreads();
        }
        #pragma unroll
        for (int i = 0; i < 8; i++) {
            long row = (bm + ty*8 + i) * (long)GK + bn2 + tx*8;
            *(float4*)&C[row]   = make_float4(acc[i][0],acc[i][1],acc[i][2],acc[i][3]);
            *(float4*)&C[row+4] = make_float4(acc[i][4],acc[i][5],acc[i][6],acc[i][7]);
        }
    }
#endif
}

// ---------------------------------------------------------------------------
// Fused transpose + tf32-round for all 4 weights (grid.z picks the weight)
// ---------------------------------------------------------------------------
__global__ __launch_bounds__(256) void transpose_cvt4(
    const float* __restrict__ W0, const float* __restrict__ W1,
    const float* __restrict__ W2, const float* __restrict__ W3,
    float* __restrict__ Wt)
{
    __shared__ float t[32][33];
    const float* W = (blockIdx.z == 0) ? W0 : (blockIdx.z == 1) ? W1
                   : (blockIdx.z == 2) ? W2 : W3;
    float* T = Wt + (long)blockIdx.z * DMOD * DMOD;
    const int tx = threadIdx.x, ty = threadIdx.y;
    const int n0 = blockIdx.x * 32, k0 = blockIdx.y * 32;
    #pragma unroll
    for (int i = 0; i < 4; i++)
        t[ty + 8*i][tx] = W[(long)(k0 + ty + 8*i) * DMOD + n0 + tx];
    __syncthreads();
    #pragma unroll
    for (int i = 0; i < 4; i++)
        T[(long)(n0 + ty + 8*i) * DMOD + k0 + tx] = cvt_tf32(t[tx][ty + 8*i]);
}

// ---------------------------------------------------------------------------
// tcgen05 flash attention (causal) — unchanged from R5
// ---------------------------------------------------------------------------
#define AT_SQ    3072
#define AT_SK    (AT_SQ + 32768)
#define AT_SV    (AT_SK + 65536)
#define AT_SP    (AT_SV + 32768)
#define AT_SMEM  (AT_SP + 65536)           // 199680

__global__ __launch_bounds__(256)
void flash_attn_tc(const float* __restrict__ Qg, const float* __restrict__ Kg,
                   const float* __restrict__ Vg, float* __restrict__ Og)
{
    extern __shared__ char smem[];
    const int tid = threadIdx.x;
    const int qx = blockIdx.x, h = blockIdx.y, b = blockIdx.z;

#if USE_TC
    const uint32_t smem_base = smem_u32(smem);
    const int wid = tid >> 5;
    const int lid = tid & 31;
    const int wg  = wid >> 2;
    const int row = (wid & 3) * 32 + lid;
    const uint32_t mb_s = smem_base + 16;
    const uint32_t mb_o = smem_base + 32;
    float* red_m = (float*)(smem + 1024);
    float* red_s = (float*)(smem + 2048);

    if (wid == 0) { TC_ALLOC(smem_base, 256); TC_RELINQ(); }
    if (tid == 0) { MBAR_INIT(mb_s, 1); MBAR_INIT(mb_o, 1); }
    __syncthreads();
    uint32_t tmem;
    asm volatile("ld.shared.b32 %0, [%1];" : "=r"(tmem) : "r"(smem_base));
    const uint32_t tmem_S = tmem;
    const uint32_t tmem_O = tmem + 128;

    const long rowbase = (long)(b * SEQ) * DMOD + h * 64;
    const int q0 = qx * 128;
    const int r8  = tid >> 3;
    const int kk8 = (tid & 7) * 4;

    #pragma unroll
    for (int s = 0; s < 2; s++)
        #pragma unroll
        for (int p = 0; p < 4; p++) {
            int rr = p * 32 + r8;
            uint32_t off = (uint32_t)(rr * 128 + kk8 * 4);
            uint32_t sw  = off ^ ((off >> 3) & 0x70);
            CP_ASYNC16(smem_base + AT_SQ + s*16384 + sw,
                       &Qg[rowbase + (long)(q0 + rr) * DMOD + s*32 + kk8]);
        }
    CP_COMMIT();
    #pragma unroll
    for (int s = 0; s < 2; s++)
        #pragma unroll
        for (int p = 0; p < 4; p++) {
            int rr = p * 32 + r8;
            uint32_t off = (uint32_t)(rr * 128 + kk8 * 4);
            uint32_t sw  = off ^ ((off >> 3) & 0x70);
            CP_ASYNC16(smem_base + AT_SK + s*16384 + sw,
                       &Kg[rowbase + (long)rr * DMOD + s*32 + kk8]);
        }
    CP_COMMIT();

    const int cbase = wg * 64;
    const int row_g = q0 + row;
    float mrow = -1e30f, lrow = 0.f, alpha_prev = 1.f;
    float acc[32];
    #pragma unroll
    for (int j = 0; j < 32; j++) acc[j] = 0.f;
    uint32_t ph_s = 0, ph_o = 0;
    const float scaling = 0.125f;

    CP_WAIT0();
    __syncthreads();

    for (int kt = 0; kt <= qx; kt++) {
        const int kb = kt & 1;
        const int k0 = kt * 128;

        if (wid == 0 && elect_one()) {
            FENCE_ASYNC_SHARED();
            TC_FENCE_AFTER();
            #pragma unroll
            for (int s = 0; s < 2; s++) {
                uint64_t qd = make_desc(smem_base + AT_SQ + s*16384);
                uint64_t kd = make_desc(smem_base + AT_SK + kb*32768 + s*16384);
                #pragma unroll
                for (int k = 0; k < 4; k++)
                    mma_tf32_ss(tmem_S, qd + k*2, kd + k*2, IDESC_N128, (s|k) != 0);
            }
            TC_COMMIT(mb_s);
        }

        if (kt < qx) {
            const int nk0 = k0 + 128;
            #pragma unroll
            for (int s = 0; s < 2; s++)
                #pragma unroll
                for (int p = 0; p < 4; p++) {
                    int rr = p * 32 + r8;
                    uint32_t off = (uint32_t)(rr * 128 + kk8 * 4);
                    uint32_t sw  = off ^ ((off >> 3) & 0x70);
                    CP_ASYNC16(smem_base + AT_SK + (kb^1)*32768 + s*16384 + sw,
                               &Kg[rowbase + (long)(nk0 + rr) * DMOD + s*32 + kk8]);
                }
            CP_COMMIT();
        }

        if (kt > 0) {
            MBAR_WAIT(mb_o, ph_o); ph_o ^= 1;
            TC_FENCE_AFTER();
            uint32_t du[32];
            TC_LD_X32(du, tmem_O + wg * 32);
            TC_WAIT_LD();
            TC_FENCE_BEFORE();
            #pragma unroll
            for (int j = 0; j < 32; j++)
                acc[j] = acc[j] * alpha_prev + __uint_as_float(du[j]);
        }

        {
            const int dv4 = (tid & 15) * 4;
            const int kv0 = tid >> 4;
            #pragma unroll
            for (int it = 0; it < 8; it++) {
                int kv = kv0 + it * 16;
                float4 v = *(const float4*)&Vg[rowbase + (long)(k0 + kv) * DMOD + dv4];
                char* basep = smem + AT_SV + (kv >> 5) * 8192;
                int within = kv & 31;
                float vv[4] = {v.x, v.y, v.z, v.w};
                #pragma unroll
                for (int j = 0; j < 4; j++) {
                    uint32_t off = (uint32_t)((dv4 + j) * 128 + within * 4);
                    uint32_t sw  = off ^ ((off >> 3) & 0x70);
                    *(float*)(basep + sw) = vv[j];
                }
            }
        }

        MBAR_WAIT(mb_s, ph_s); ph_s ^= 1;
        TC_FENCE_AFTER();
        uint32_t u0[32], u1[32];
        TC_LD_X32(u0, tmem_S + cbase);
        TC_LD_X32(u1, tmem_S + cbase + 32);
        TC_WAIT_LD();
        TC_FENCE_BEFORE();

        float sv[64];
        #pragma unroll
        for (int j = 0; j < 32; j++) {
            sv[j]      = __uint_as_float(u0[j]) * scaling;
            sv[32 + j] = __uint_as_float(u1[j]) * scaling;
        }
        if (kt == qx) {
            #pragma unroll
            for (int j = 0; j < 64; j++)
                if (k0 + cbase + j > row_g) sv[j] = -1e30f;
        }

        float lm = sv[0];
        #pragma unroll
        for (int j = 1; j < 64; j++) lm = fmaxf(lm, sv[j]);
        red_m[wg * 128 + row] = lm;
        __syncthreads();
        float mtile = fmaxf(red_m[row], red_m[128 + row]);
        float mnew  = fmaxf(mrow, mtile);
        float alpha = __expf(mrow - mnew);

        float ls = 0.f;
        #pragma unroll
        for (int j = 0; j < 64; j++) {
            float p = __expf(sv[j] - mnew);
            sv[j] = p;
            ls += p;
        }
        red_s[wg * 128 + row] = ls;

        #pragma unroll
        for (int g = 0; g < 16; g++) {
            int c = cbase + g * 4;
            char* basep = smem + AT_SP + (c >> 5) * 16384;
            uint32_t off = (uint32_t)(row * 128 + (c & 31) * 4);
            uint32_t sw  = off ^ ((off >> 3) & 0x70);
            *(float4*)(basep + sw) = make_float4(
                cvt_tf32(sv[g*4+0]), cvt_tf32(sv[g*4+1]),
                cvt_tf32(sv[g*4+2]), cvt_tf32(sv[g*4+3]));
        }

        CP_WAIT0();
        __syncthreads();

        float ltile = red_s[row] + red_s[128 + row];
        lrow = lrow * alpha + ltile;
        mrow = mnew;
        alpha_prev = alpha;

        if (wid == 0 && elect_one()) {
            FENCE_ASYNC_SHARED();
            TC_FENCE_AFTER();
            #pragma unroll
            for (int c = 0; c < 4; c++) {
                uint64_t pd = make_desc(smem_base + AT_SP + c*16384);
                uint64_t vd = make_desc(smem_base + AT_SV + c*8192);
                #pragma unroll
                for (int k = 0; k < 4; k++)
                    mma_tf32_ss(tmem_O, pd + k*2, vd + k*2, IDESC_N64, (c|k) != 0);
            }
            TC_COMMIT(mb_o);
        }
    }

    MBAR_WAIT(mb_o, ph_o); ph_o ^= 1;
    TC_FENCE_AFTER();
    {
        uint32_t du[32];
        TC_LD_X32(du, tmem_O + wg * 32);
        TC_WAIT_LD();
        TC_FENCE_BEFORE();
        #pragma unroll
        for (int j = 0; j < 32; j++)
            acc[j] = acc[j] * alpha_prev + __uint_as_float(du[j]);

        float inv = 1.f / lrow;
        float* orow = &Og[rowbase + (long)(q0 + row) * DMOD + wg * 32];
        #pragma unroll
        for (int g = 0; g < 8; g++)
            *(float4*)&orow[g * 4] = make_float4(
                acc[g*4+0]*inv, acc[g*4+1]*inv,
                acc[g*4+2]*inv, acc[g*4+3]*inv);
    }
    __syncthreads();
    if (tid == 0) { MBAR_INVAL(mb_s); MBAR_INVAL(mb_o); }
    if (wid == 0) TC_DEALLOC(tmem, 256);

#else  // trivial fallback
    if (tid < 128) {
        const long rowbase = (long)(b * SEQ) * DMOD + h * 64;
        const int q = qx * 128 + tid;
        float qreg[64];
        #pragma unroll
        for (int d = 0; d < 64; d++) qreg[d] = Qg[rowbase + (long)q * DMOD + d];
        float m = -1e30f, l = 0.f, acc[64];
        #pragma unroll
        for (int d = 0; d < 64; d++) acc[d] = 0.f;
        for (int kv = 0; kv <= q; kv++) {
            const float* kr = &Kg[rowbase + (long)kv * DMOD];
            float s = 0.f;
            for (int d = 0; d < 64; d++) s += qreg[d] * kr[d];
            s *= 0.125f;
            float mn = fmaxf(m, s);
            float al = __expf(m - mn), p = __expf(s - mn);
            l = l * al + p;
            const float* vr = &Vg[rowbase + (long)kv * DMOD];
            for (int d = 0; d < 64; d++) acc[d] = acc[d] * al + p * vr[d];
            m = mn;
        }
        float inv = 1.f / l;
        for (int d = 0; d < 64; d++)
            Og[rowbase + (long)q * DMOD + d] = acc[d] * inv;
    }
#endif
}

// ---------------------------------------------------------------------------
// Host launcher
// ---------------------------------------------------------------------------
extern "C" void kernel_launch(void* const* d_in, const int* in_sizes, int n_in,
                              void* d_out, int out_size)
{
    const float* queries = (const float*)d_in[0];
    const float* keys    = (const float*)d_in[1];
    const float* values  = (const float*)d_in[2];
    // d_in[3] = mask — causal, analytic
    const float* W_Q = (const float*)d_in[4];
    const float* W_K = (const float*)d_in[5];
    const float* W_V = (const float*)d_in[6];
    const float* W_O = (const float*)d_in[7];
    float* out = (float*)d_out;

    float *Qb, *Kb, *Vb, *Ab, *Wt;
    cudaGetSymbolAddress((void**)&Qb, g_Q);
    cudaGetSymbolAddress((void**)&Kb, g_K);
    cudaGetSymbolAddress((void**)&Vb, g_V);
    cudaGetSymbolAddress((void**)&Ab, g_A);
    cudaGetSymbolAddress((void**)&Wt, g_Wt4);

    cudaFuncSetAttribute(gemm_tn, cudaFuncAttributeMaxDynamicSharedMemorySize,
                         GEMM_SMEM);
    cudaFuncSetAttribute(flash_attn_tc, cudaFuncAttributeMaxDynamicSharedMemorySize,
                         AT_SMEM);

    const long WSZ = (long)DMOD * DMOD;
    dim3 tgrid(32, 32, 4), tblk(32, 8);
    dim3 ggrid(DMOD / 256, MROWS / 128);   // (4, 64)

    transpose_cvt4<<<tgrid, tblk>>>(W_Q, W_K, W_V, W_O, Wt);

    gemm_tn<<<ggrid, 256, GEMM_SMEM>>>(queries, Wt + 0*WSZ, Qb, 1);
    gemm_tn<<<ggrid, 256, GEMM_SMEM>>>(keys,    Wt + 1*WSZ, Kb, 1);
    gemm_tn<<<ggrid, 256, GEMM_SMEM>>>(values,  Wt + 2*WSZ, Vb, 1);

    dim3 agrid(SEQ / 128, NHEAD, BATCH);
    flash_attn_tc<<<agrid, 256, AT_SMEM>>>(Qb, Kb, Vb, Ab);

    gemm_tn<<<ggrid, 256, GEMM_SMEM>>>(Ab, Wt + 3*WSZ, out, 0);
}